// round 1
// baseline (speedup 1.0000x reference)
#include <cuda_runtime.h>
#include <math.h>

#define N_EMBD 1024
#define N_HEAD 16
#define HEADD  64
#define BATCH  4
#define SEQ    2048
#define ROWS   (BATCH * SEQ)          // 8192
#define C3     (3 * N_EMBD)           // 3072

// scratch (allocation-free rule: device globals)
__device__ float g_qkv[(size_t)ROWS * C3];      // [8192, 3072]
__device__ float g_att[(size_t)ROWS * N_EMBD];  // [8192, 1024]

// ---------------------------------------------------------------------------
// SGEMM + bias: C[M,N] = A[M,K] @ B[K,N] + bias[N]
// 128x128 block tile, BK=8, 256 threads, 8x8 per-thread micro-tile.
// M,N,K all multiples of the tile sizes here (no bounds checks).
// ---------------------------------------------------------------------------
__global__ __launch_bounds__(256) void sgemm_bias(
    const float* __restrict__ A, const float* __restrict__ B,
    const float* __restrict__ bias, float* __restrict__ C,
    int M, int N, int K)
{
    __shared__ float As[8][128];   // transposed: As[k][m]
    __shared__ float Bs[8][128];

    const int tid = threadIdx.x;
    const int tx = tid & 15;       // 0..15 -> N
    const int ty = tid >> 4;       // 0..15 -> M

    const int m0 = blockIdx.y * 128;
    const int n0 = blockIdx.x * 128;

    // A tile loads: 128 rows x 8 cols, one float4 per thread
    const int arow = tid >> 1;
    const int acol = (tid & 1) * 4;
    // B tile loads: 8 rows x 128 cols, one float4 per thread
    const int brow = tid >> 5;
    const int bcol = (tid & 31) * 4;

    const float* Ab = A + (size_t)(m0 + arow) * K + acol;
    const float* Bb = B + (size_t)brow * N + n0 + bcol;

    float acc[8][8];
#pragma unroll
    for (int i = 0; i < 8; i++)
#pragma unroll
        for (int j = 0; j < 8; j++) acc[i][j] = 0.f;

    for (int k0 = 0; k0 < K; k0 += 8) {
        float4 av = *(const float4*)(Ab + k0);
        As[acol + 0][arow] = av.x;
        As[acol + 1][arow] = av.y;
        As[acol + 2][arow] = av.z;
        As[acol + 3][arow] = av.w;
        *(float4*)&Bs[brow][bcol] = *(const float4*)(Bb + (size_t)k0 * N);
        __syncthreads();

#pragma unroll
        for (int kk = 0; kk < 8; kk++) {
            float4 a0 = *(float4*)&As[kk][ty * 8];
            float4 a1 = *(float4*)&As[kk][ty * 8 + 4];
            float4 b0 = *(float4*)&Bs[kk][tx * 8];
            float4 b1 = *(float4*)&Bs[kk][tx * 8 + 4];
            float ar[8] = {a0.x, a0.y, a0.z, a0.w, a1.x, a1.y, a1.z, a1.w};
            float br[8] = {b0.x, b0.y, b0.z, b0.w, b1.x, b1.y, b1.z, b1.w};
#pragma unroll
            for (int i = 0; i < 8; i++)
#pragma unroll
                for (int j = 0; j < 8; j++)
                    acc[i][j] = fmaf(ar[i], br[j], acc[i][j]);
        }
        __syncthreads();
    }

    const int ccol = n0 + tx * 8;
    float4 bi0 = *(const float4*)(bias + ccol);
    float4 bi1 = *(const float4*)(bias + ccol + 4);
#pragma unroll
    for (int i = 0; i < 8; i++) {
        const int crow = m0 + ty * 8 + i;
        float4 o0, o1;
        o0.x = acc[i][0] + bi0.x; o0.y = acc[i][1] + bi0.y;
        o0.z = acc[i][2] + bi0.z; o0.w = acc[i][3] + bi0.w;
        o1.x = acc[i][4] + bi1.x; o1.y = acc[i][5] + bi1.y;
        o1.z = acc[i][6] + bi1.z; o1.w = acc[i][7] + bi1.w;
        *(float4*)(C + (size_t)crow * N + ccol) = o0;
        *(float4*)(C + (size_t)crow * N + ccol + 4) = o1;
    }
}

// ---------------------------------------------------------------------------
// Flash attention, causal, fp32.
// grid: (T/64, B*H). block: 256 threads (16x16), each owns 4 rows x 4 cols.
// Smem: Qt (transposed 64x64), KV (Kt transposed, then V direct), Pt.
// Exactly 48KB static shared.
// ---------------------------------------------------------------------------
__global__ __launch_bounds__(256) void attn_kernel(
    const float* __restrict__ qkv, float* __restrict__ att)
{
    __shared__ float Qt[64][64];
    __shared__ float KV[64][64];
    __shared__ float Pt[64][64];

    const int qb = blockIdx.x;
    const int b  = blockIdx.y >> 4;
    const int h  = blockIdx.y & 15;

    const int tid = threadIdx.x;
    const int tx = tid & 15;   // col group (c or d)
    const int ty = tid >> 4;   // row group (r)
    const int r0 = ty * 4;
    const int c0 = tx * 4;

    const float* qbase = qkv + ((size_t)(b * SEQ + qb * 64)) * C3 + h * HEADD;

    // load Q tile transposed: Qt[d][r]
    for (int i = tid; i < 64 * 16; i += 256) {
        int r  = i >> 4;
        int c4 = (i & 15) << 2;
        float4 v = *(const float4*)(qbase + (size_t)r * C3 + c4);
        Qt[c4 + 0][r] = v.x; Qt[c4 + 1][r] = v.y;
        Qt[c4 + 2][r] = v.z; Qt[c4 + 3][r] = v.w;
    }

    float m_i[4], l_i[4], o[4][4];
#pragma unroll
    for (int i = 0; i < 4; i++) {
        m_i[i] = -1e30f; l_i[i] = 0.f;
#pragma unroll
        for (int j = 0; j < 4; j++) o[i][j] = 0.f;
    }

    const float scale = 0.125f;   // 1/sqrt(64)

    for (int jb = 0; jb <= qb; jb++) {
        const float* kbase = qkv + ((size_t)(b * SEQ + jb * 64)) * C3 + N_EMBD + h * HEADD;
        __syncthreads();   // previous iter's V reads done
        // load K tile transposed: Kt[d][c] into KV
        for (int i = tid; i < 64 * 16; i += 256) {
            int r  = i >> 4;
            int c4 = (i & 15) << 2;
            float4 v = *(const float4*)(kbase + (size_t)r * C3 + c4);
            KV[c4 + 0][r] = v.x; KV[c4 + 1][r] = v.y;
            KV[c4 + 2][r] = v.z; KV[c4 + 3][r] = v.w;
        }
        __syncthreads();

        // S = Q K^T (4x4 per thread)
        float s[4][4];
#pragma unroll
        for (int i = 0; i < 4; i++)
#pragma unroll
            for (int j = 0; j < 4; j++) s[i][j] = 0.f;

#pragma unroll 8
        for (int d = 0; d < 64; d++) {
            float4 qv = *(float4*)&Qt[d][r0];
            float4 kv = *(float4*)&KV[d][c0];
            float qa[4] = {qv.x, qv.y, qv.z, qv.w};
            float ka[4] = {kv.x, kv.y, kv.z, kv.w};
#pragma unroll
            for (int i = 0; i < 4; i++)
#pragma unroll
                for (int j = 0; j < 4; j++)
                    s[i][j] = fmaf(qa[i], ka[j], s[i][j]);
        }

        // scale + causal mask (only needed on diagonal block)
        if (jb == qb) {
#pragma unroll
            for (int i = 0; i < 4; i++)
#pragma unroll
                for (int j = 0; j < 4; j++)
                    s[i][j] = (c0 + j > r0 + i) ? -1e30f : s[i][j] * scale;
        } else {
#pragma unroll
            for (int i = 0; i < 4; i++)
#pragma unroll
                for (int j = 0; j < 4; j++)
                    s[i][j] *= scale;
        }

        // online softmax update
        float alpha[4];
#pragma unroll
        for (int i = 0; i < 4; i++) {
            float mx = fmaxf(fmaxf(s[i][0], s[i][1]), fmaxf(s[i][2], s[i][3]));
#pragma unroll
            for (int mk = 1; mk < 16; mk <<= 1)
                mx = fmaxf(mx, __shfl_xor_sync(0xffffffffu, mx, mk));
            float m_new = fmaxf(m_i[i], mx);
            alpha[i] = __expf(m_i[i] - m_new);
            float rs = 0.f;
#pragma unroll
            for (int j = 0; j < 4; j++) {
                s[i][j] = __expf(s[i][j] - m_new);
                rs += s[i][j];
            }
#pragma unroll
            for (int mk = 1; mk < 16; mk <<= 1)
                rs += __shfl_xor_sync(0xffffffffu, rs, mk);
            l_i[i] = l_i[i] * alpha[i] + rs;
            m_i[i] = m_new;
#pragma unroll
            for (int j = 0; j < 4; j++) o[i][j] *= alpha[i];
        }

        __syncthreads();   // done reading Kt; safe to overwrite KV with V
        // write Pt[c][r]; load V direct: KV[c][d]
#pragma unroll
        for (int i = 0; i < 4; i++)
#pragma unroll
            for (int j = 0; j < 4; j++)
                Pt[c0 + j][r0 + i] = s[i][j];

        const float* vbase = qkv + ((size_t)(b * SEQ + jb * 64)) * C3 + 2 * N_EMBD + h * HEADD;
        for (int i = tid; i < 64 * 16; i += 256) {
            int r  = i >> 4;
            int c4 = (i & 15) << 2;
            *(float4*)&KV[r][c4] = *(const float4*)(vbase + (size_t)r * C3 + c4);
        }
        __syncthreads();

        // O += P @ V
#pragma unroll 8
        for (int c = 0; c < 64; c++) {
            float4 pv = *(float4*)&Pt[c][r0];
            float4 vv = *(float4*)&KV[c][c0];
            float pa[4] = {pv.x, pv.y, pv.z, pv.w};
            float va[4] = {vv.x, vv.y, vv.z, vv.w};
#pragma unroll
            for (int i = 0; i < 4; i++)
#pragma unroll
                for (int j = 0; j < 4; j++)
                    o[i][j] = fmaf(pa[i], va[j], o[i][j]);
        }
    }

    // normalize and write out: att[b*SEQ + qb*64 + r][h*64 + d]
#pragma unroll
    for (int i = 0; i < 4; i++) {
        float inv = 1.f / l_i[i];
        float4 ov;
        ov.x = o[i][0] * inv; ov.y = o[i][1] * inv;
        ov.z = o[i][2] * inv; ov.w = o[i][3] * inv;
        size_t row = (size_t)(b * SEQ + qb * 64 + r0 + i);
        *(float4*)(g_att + row * N_EMBD + h * HEADD + c0) = ov;
    }
}

// ---------------------------------------------------------------------------
extern "C" void kernel_launch(void* const* d_in, const int* in_sizes, int n_in,
                              void* d_out, int out_size)
{
    const float* x     = (const float*)d_in[0];
    const float* W_qkv = (const float*)d_in[1];
    const float* b_qkv = (const float*)d_in[2];
    const float* W_out = (const float*)d_in[3];
    const float* b_out = (const float*)d_in[4];
    float* out = (float*)d_out;

    float* qkv; float* att;
    cudaGetSymbolAddress((void**)&qkv, g_qkv);
    cudaGetSymbolAddress((void**)&att, g_att);

    // 1) qkv = x @ W_qkv + b_qkv   [8192,3072]
    sgemm_bias<<<dim3(C3 / 128, ROWS / 128), 256>>>(x, W_qkv, b_qkv, qkv,
                                                    ROWS, C3, N_EMBD);
    // 2) attention -> g_att [8192,1024]
    attn_kernel<<<dim3(SEQ / 64, BATCH * N_HEAD), 256>>>(qkv, att);
    // 3) out = att @ W_out + b_out
    sgemm_bias<<<dim3(N_EMBD / 128, ROWS / 128), 256>>>(att, W_out, b_out, out,
                                                        ROWS, N_EMBD, N_EMBD);
}

// round 2
// speedup vs baseline: 1.4978x; 1.4978x over previous
#include <cuda_runtime.h>
#include <cstdint>
#include <math.h>

#define N_EMBD 1024
#define N_HEAD 16
#define HEADD  64
#define BATCH  4
#define SEQ    2048
#define ROWS   (BATCH * SEQ)          // 8192
#define C3     (3 * N_EMBD)           // 3072

// scratch (allocation-free rule: device globals)
__device__ float g_qkv[(size_t)ROWS * C3];      // [8192, 3072]
__device__ float g_att[(size_t)ROWS * N_EMBD];  // [8192, 1024]

__device__ __forceinline__ float to_tf32(float x) {
    uint32_t o;
    asm("cvt.rna.tf32.f32 %0, %1;" : "=r"(o) : "f"(x));
    return __uint_as_float(o);
}

__device__ __forceinline__ void mma_tf32(float* d, const uint32_t* a, const uint32_t* b) {
    asm volatile(
        "mma.sync.aligned.m16n8k8.row.col.f32.tf32.tf32.f32 "
        "{%0,%1,%2,%3}, {%4,%5,%6,%7}, {%8,%9}, {%0,%1,%2,%3};"
        : "+f"(d[0]), "+f"(d[1]), "+f"(d[2]), "+f"(d[3])
        : "r"(a[0]), "r"(a[1]), "r"(a[2]), "r"(a[3]), "r"(b[0]), "r"(b[1]));
}

// ---------------------------------------------------------------------------
// TF32 tensor-core GEMM + bias: C[M,N] = A[M,K] @ B[K,N] + bias[N]
// 128x128 tile, BK=32, 256 threads = 8 warps (2x4), each warp 64x32 out.
// fp32 accumulate, fp32 bias epilogue.
// ---------------------------------------------------------------------------
__global__ __launch_bounds__(256) void gemm_tf32(
    const float* __restrict__ A, const float* __restrict__ B,
    const float* __restrict__ bias, float* __restrict__ C,
    int M, int N, int K)
{
    __shared__ float As[128][36];   // [m][k], pad->conflict-free frag loads
    __shared__ float Bs[32][136];   // [k][n], pad->conflict-free frag loads

    const int tid  = threadIdx.x;
    const int lane = tid & 31;
    const int warp = tid >> 5;
    const int wm   = (warp >> 2) * 64;   // warp m offset in tile
    const int wn   = (warp & 3) * 32;    // warp n offset in tile

    const int m0 = blockIdx.y * 128;
    const int n0 = blockIdx.x * 128;

    const int gid = lane >> 2;   // group id 0..7
    const int gtd = lane & 3;    // tid in group 0..3

    float acc[4][4][4];
#pragma unroll
    for (int mi = 0; mi < 4; mi++)
#pragma unroll
        for (int ni = 0; ni < 4; ni++)
#pragma unroll
            for (int r = 0; r < 4; r++) acc[mi][ni][r] = 0.f;

    float4 pa[4], pb[4];

    // global-load slot mapping (1024 float4 slots each for A and B tiles)
    // A slot s: row = s>>3, kc = (s&7)*4 ; B slot s: kr = s>>5, nc = (s&31)*4
#define LDG_TILES(k0)                                                          \
    {                                                                          \
        _Pragma("unroll")                                                      \
        for (int i = 0; i < 4; i++) {                                          \
            int s = tid + i * 256;                                             \
            pa[i] = *(const float4*)(A + (size_t)(m0 + (s >> 3)) * K + (k0) + ((s & 7) << 2)); \
            pb[i] = *(const float4*)(B + (size_t)((k0) + (s >> 5)) * N + n0 + ((s & 31) << 2)); \
        }                                                                      \
    }

#define STS_TILES()                                                            \
    {                                                                          \
        _Pragma("unroll")                                                      \
        for (int i = 0; i < 4; i++) {                                          \
            int s   = tid + i * 256;                                           \
            int ar  = s >> 3, akc = (s & 7) << 2;                              \
            As[ar][akc + 0] = to_tf32(pa[i].x);                                \
            As[ar][akc + 1] = to_tf32(pa[i].y);                                \
            As[ar][akc + 2] = to_tf32(pa[i].z);                                \
            As[ar][akc + 3] = to_tf32(pa[i].w);                                \
            int bkr = s >> 5, bnc = (s & 31) << 2;                             \
            float4 bv;                                                         \
            bv.x = to_tf32(pb[i].x); bv.y = to_tf32(pb[i].y);                  \
            bv.z = to_tf32(pb[i].z); bv.w = to_tf32(pb[i].w);                  \
            *(float4*)&Bs[bkr][bnc] = bv;                                      \
        }                                                                      \
    }

    LDG_TILES(0);
    STS_TILES();
    __syncthreads();

    for (int k0 = 0; k0 < K; k0 += 32) {
        const bool has_next = (k0 + 32) < K;
        if (has_next) LDG_TILES(k0 + 32);

#pragma unroll
        for (int kk = 0; kk < 4; kk++) {
            const int kb = kk * 8;
            uint32_t af[4][4];
#pragma unroll
            for (int mi = 0; mi < 4; mi++) {
                const int mr = wm + mi * 16 + gid;
                const int kc = kb + gtd;
                af[mi][0] = __float_as_uint(As[mr][kc]);
                af[mi][1] = __float_as_uint(As[mr + 8][kc]);
                af[mi][2] = __float_as_uint(As[mr][kc + 4]);
                af[mi][3] = __float_as_uint(As[mr + 8][kc + 4]);
            }
            uint32_t bf[4][2];
#pragma unroll
            for (int ni = 0; ni < 4; ni++) {
                const int nc = wn + ni * 8 + gid;
                const int kr = kb + gtd;
                bf[ni][0] = __float_as_uint(Bs[kr][nc]);
                bf[ni][1] = __float_as_uint(Bs[kr + 4][nc]);
            }
#pragma unroll
            for (int mi = 0; mi < 4; mi++)
#pragma unroll
                for (int ni = 0; ni < 4; ni++)
                    mma_tf32(acc[mi][ni], af[mi], bf[ni]);
        }

        __syncthreads();
        if (has_next) {
            STS_TILES();
            __syncthreads();
        }
    }

    // epilogue: fp32 bias add, float2 stores
#pragma unroll
    for (int mi = 0; mi < 4; mi++) {
#pragma unroll
        for (int ni = 0; ni < 4; ni++) {
            const int row = m0 + wm + mi * 16 + gid;
            const int col = n0 + wn + ni * 8 + (gtd << 1);
            const float b0 = bias[col];
            const float b1 = bias[col + 1];
            float2 v0, v1;
            v0.x = acc[mi][ni][0] + b0; v0.y = acc[mi][ni][1] + b1;
            v1.x = acc[mi][ni][2] + b0; v1.y = acc[mi][ni][3] + b1;
            *(float2*)(C + (size_t)row * N + col)       = v0;
            *(float2*)(C + (size_t)(row + 8) * N + col) = v1;
        }
    }
#undef LDG_TILES
#undef STS_TILES
}

// ---------------------------------------------------------------------------
// Flash attention, causal, fp32 (unchanged from round 1).
// ---------------------------------------------------------------------------
__global__ __launch_bounds__(256) void attn_kernel(
    const float* __restrict__ qkv, float* __restrict__ att)
{
    __shared__ float Qt[64][64];
    __shared__ float KV[64][64];
    __shared__ float Pt[64][64];

    const int qb = blockIdx.x;
    const int b  = blockIdx.y >> 4;
    const int h  = blockIdx.y & 15;

    const int tid = threadIdx.x;
    const int tx = tid & 15;
    const int ty = tid >> 4;
    const int r0 = ty * 4;
    const int c0 = tx * 4;

    const float* qbase = qkv + ((size_t)(b * SEQ + qb * 64)) * C3 + h * HEADD;

    for (int i = tid; i < 64 * 16; i += 256) {
        int r  = i >> 4;
        int c4 = (i & 15) << 2;
        float4 v = *(const float4*)(qbase + (size_t)r * C3 + c4);
        Qt[c4 + 0][r] = v.x; Qt[c4 + 1][r] = v.y;
        Qt[c4 + 2][r] = v.z; Qt[c4 + 3][r] = v.w;
    }

    float m_i[4], l_i[4], o[4][4];
#pragma unroll
    for (int i = 0; i < 4; i++) {
        m_i[i] = -1e30f; l_i[i] = 0.f;
#pragma unroll
        for (int j = 0; j < 4; j++) o[i][j] = 0.f;
    }

    const float scale = 0.125f;

    for (int jb = 0; jb <= qb; jb++) {
        const float* kbase = qkv + ((size_t)(b * SEQ + jb * 64)) * C3 + N_EMBD + h * HEADD;
        __syncthreads();
        for (int i = tid; i < 64 * 16; i += 256) {
            int r  = i >> 4;
            int c4 = (i & 15) << 2;
            float4 v = *(const float4*)(kbase + (size_t)r * C3 + c4);
            KV[c4 + 0][r] = v.x; KV[c4 + 1][r] = v.y;
            KV[c4 + 2][r] = v.z; KV[c4 + 3][r] = v.w;
        }
        __syncthreads();

        float s[4][4];
#pragma unroll
        for (int i = 0; i < 4; i++)
#pragma unroll
            for (int j = 0; j < 4; j++) s[i][j] = 0.f;

#pragma unroll 8
        for (int d = 0; d < 64; d++) {
            float4 qv = *(float4*)&Qt[d][r0];
            float4 kv = *(float4*)&KV[d][c0];
            float qa[4] = {qv.x, qv.y, qv.z, qv.w};
            float ka[4] = {kv.x, kv.y, kv.z, kv.w};
#pragma unroll
            for (int i = 0; i < 4; i++)
#pragma unroll
                for (int j = 0; j < 4; j++)
                    s[i][j] = fmaf(qa[i], ka[j], s[i][j]);
        }

        if (jb == qb) {
#pragma unroll
            for (int i = 0; i < 4; i++)
#pragma unroll
                for (int j = 0; j < 4; j++)
                    s[i][j] = (c0 + j > r0 + i) ? -1e30f : s[i][j] * scale;
        } else {
#pragma unroll
            for (int i = 0; i < 4; i++)
#pragma unroll
                for (int j = 0; j < 4; j++)
                    s[i][j] *= scale;
        }

        float alpha[4];
#pragma unroll
        for (int i = 0; i < 4; i++) {
            float mx = fmaxf(fmaxf(s[i][0], s[i][1]), fmaxf(s[i][2], s[i][3]));
#pragma unroll
            for (int mk = 1; mk < 16; mk <<= 1)
                mx = fmaxf(mx, __shfl_xor_sync(0xffffffffu, mx, mk));
            float m_new = fmaxf(m_i[i], mx);
            alpha[i] = __expf(m_i[i] - m_new);
            float rs = 0.f;
#pragma unroll
            for (int j = 0; j < 4; j++) {
                s[i][j] = __expf(s[i][j] - m_new);
                rs += s[i][j];
            }
#pragma unroll
            for (int mk = 1; mk < 16; mk <<= 1)
                rs += __shfl_xor_sync(0xffffffffu, rs, mk);
            l_i[i] = l_i[i] * alpha[i] + rs;
            m_i[i] = m_new;
#pragma unroll
            for (int j = 0; j < 4; j++) o[i][j] *= alpha[i];
        }

        __syncthreads();
#pragma unroll
        for (int i = 0; i < 4; i++)
#pragma unroll
            for (int j = 0; j < 4; j++)
                Pt[c0 + j][r0 + i] = s[i][j];

        const float* vbase = qkv + ((size_t)(b * SEQ + jb * 64)) * C3 + 2 * N_EMBD + h * HEADD;
        for (int i = tid; i < 64 * 16; i += 256) {
            int r  = i >> 4;
            int c4 = (i & 15) << 2;
            *(float4*)&KV[r][c4] = *(const float4*)(vbase + (size_t)r * C3 + c4);
        }
        __syncthreads();

#pragma unroll 8
        for (int c = 0; c < 64; c++) {
            float4 pv = *(float4*)&Pt[c][r0];
            float4 vv = *(float4*)&KV[c][c0];
            float pa[4] = {pv.x, pv.y, pv.z, pv.w};
            float va[4] = {vv.x, vv.y, vv.z, vv.w};
#pragma unroll
            for (int i = 0; i < 4; i++)
#pragma unroll
                for (int j = 0; j < 4; j++)
                    o[i][j] = fmaf(pa[i], va[j], o[i][j]);
        }
    }

#pragma unroll
    for (int i = 0; i < 4; i++) {
        float inv = 1.f / l_i[i];
        float4 ov;
        ov.x = o[i][0] * inv; ov.y = o[i][1] * inv;
        ov.z = o[i][2] * inv; ov.w = o[i][3] * inv;
        size_t row = (size_t)(b * SEQ + qb * 64 + r0 + i);
        *(float4*)(g_att + row * N_EMBD + h * HEADD + c0) = ov;
    }
}

// ---------------------------------------------------------------------------
extern "C" void kernel_launch(void* const* d_in, const int* in_sizes, int n_in,
                              void* d_out, int out_size)
{
    const float* x     = (const float*)d_in[0];
    const float* W_qkv = (const float*)d_in[1];
    const float* b_qkv = (const float*)d_in[2];
    const float* W_out = (const float*)d_in[3];
    const float* b_out = (const float*)d_in[4];
    float* out = (float*)d_out;

    float* qkv; float* att;
    cudaGetSymbolAddress((void**)&qkv, g_qkv);
    cudaGetSymbolAddress((void**)&att, g_att);

    // 1) qkv = x @ W_qkv + b_qkv   [8192,3072]
    gemm_tf32<<<dim3(C3 / 128, ROWS / 128), 256>>>(x, W_qkv, b_qkv, qkv,
                                                   ROWS, C3, N_EMBD);
    // 2) attention -> g_att [8192,1024]
    attn_kernel<<<dim3(SEQ / 64, BATCH * N_HEAD), 256>>>(qkv, att);
    // 3) out = att @ W_out + b_out
    gemm_tf32<<<dim3(N_EMBD / 128, ROWS / 128), 256>>>(att, W_out, b_out, out,
                                                       ROWS, N_EMBD, N_EMBD);
}

// round 3
// speedup vs baseline: 2.9891x; 1.9957x over previous
#include <cuda_runtime.h>
#include <cstdint>
#include <math.h>

#define N_EMBD 1024
#define N_HEAD 16
#define HEADD  64
#define BATCH  4
#define SEQ    2048
#define ROWS   (BATCH * SEQ)          // 8192
#define C3     (3 * N_EMBD)           // 3072

// scratch (allocation-free rule: device globals)
__device__ float g_qkv[(size_t)ROWS * C3];      // [8192, 3072]
__device__ float g_att[(size_t)ROWS * N_EMBD];  // [8192, 1024]

__device__ __forceinline__ float to_tf32(float x) {
    uint32_t o;
    asm("cvt.rna.tf32.f32 %0, %1;" : "=r"(o) : "f"(x));
    return __uint_as_float(o);
}
__device__ __forceinline__ uint32_t to_tf32u(float x) {
    uint32_t o;
    asm("cvt.rna.tf32.f32 %0, %1;" : "=r"(o) : "f"(x));
    return o;
}

__device__ __forceinline__ void mma_tf32(float* d, const uint32_t* a, const uint32_t* b) {
    asm volatile(
        "mma.sync.aligned.m16n8k8.row.col.f32.tf32.tf32.f32 "
        "{%0,%1,%2,%3}, {%4,%5,%6,%7}, {%8,%9}, {%0,%1,%2,%3};"
        : "+f"(d[0]), "+f"(d[1]), "+f"(d[2]), "+f"(d[3])
        : "r"(a[0]), "r"(a[1]), "r"(a[2]), "r"(a[3]), "r"(b[0]), "r"(b[1]));
}

// ---------------------------------------------------------------------------
// TF32 tensor-core GEMM + bias (unchanged from round 2)
// ---------------------------------------------------------------------------
__global__ __launch_bounds__(256) void gemm_tf32(
    const float* __restrict__ A, const float* __restrict__ B,
    const float* __restrict__ bias, float* __restrict__ C,
    int M, int N, int K)
{
    __shared__ float As[128][36];
    __shared__ float Bs[32][136];

    const int tid  = threadIdx.x;
    const int lane = tid & 31;
    const int warp = tid >> 5;
    const int wm   = (warp >> 2) * 64;
    const int wn   = (warp & 3) * 32;

    const int m0 = blockIdx.y * 128;
    const int n0 = blockIdx.x * 128;

    const int gid = lane >> 2;
    const int gtd = lane & 3;

    float acc[4][4][4];
#pragma unroll
    for (int mi = 0; mi < 4; mi++)
#pragma unroll
        for (int ni = 0; ni < 4; ni++)
#pragma unroll
            for (int r = 0; r < 4; r++) acc[mi][ni][r] = 0.f;

    float4 pa[4], pb[4];

#define LDG_TILES(k0)                                                          \
    {                                                                          \
        _Pragma("unroll")                                                      \
        for (int i = 0; i < 4; i++) {                                          \
            int s = tid + i * 256;                                             \
            pa[i] = *(const float4*)(A + (size_t)(m0 + (s >> 3)) * K + (k0) + ((s & 7) << 2)); \
            pb[i] = *(const float4*)(B + (size_t)((k0) + (s >> 5)) * N + n0 + ((s & 31) << 2)); \
        }                                                                      \
    }

#define STS_TILES()                                                            \
    {                                                                          \
        _Pragma("unroll")                                                      \
        for (int i = 0; i < 4; i++) {                                          \
            int s   = tid + i * 256;                                           \
            int ar  = s >> 3, akc = (s & 7) << 2;                              \
            As[ar][akc + 0] = to_tf32(pa[i].x);                                \
            As[ar][akc + 1] = to_tf32(pa[i].y);                                \
            As[ar][akc + 2] = to_tf32(pa[i].z);                                \
            As[ar][akc + 3] = to_tf32(pa[i].w);                                \
            int bkr = s >> 5, bnc = (s & 31) << 2;                             \
            float4 bv;                                                         \
            bv.x = to_tf32(pb[i].x); bv.y = to_tf32(pb[i].y);                  \
            bv.z = to_tf32(pb[i].z); bv.w = to_tf32(pb[i].w);                  \
            *(float4*)&Bs[bkr][bnc] = bv;                                      \
        }                                                                      \
    }

    LDG_TILES(0);
    STS_TILES();
    __syncthreads();

    for (int k0 = 0; k0 < K; k0 += 32) {
        const bool has_next = (k0 + 32) < K;
        if (has_next) LDG_TILES(k0 + 32);

#pragma unroll
        for (int kk = 0; kk < 4; kk++) {
            const int kb = kk * 8;
            uint32_t af[4][4];
#pragma unroll
            for (int mi = 0; mi < 4; mi++) {
                const int mr = wm + mi * 16 + gid;
                const int kc = kb + gtd;
                af[mi][0] = __float_as_uint(As[mr][kc]);
                af[mi][1] = __float_as_uint(As[mr + 8][kc]);
                af[mi][2] = __float_as_uint(As[mr][kc + 4]);
                af[mi][3] = __float_as_uint(As[mr + 8][kc + 4]);
            }
            uint32_t bf[4][2];
#pragma unroll
            for (int ni = 0; ni < 4; ni++) {
                const int nc = wn + ni * 8 + gid;
                const int kr = kb + gtd;
                bf[ni][0] = __float_as_uint(Bs[kr][nc]);
                bf[ni][1] = __float_as_uint(Bs[kr + 4][nc]);
            }
#pragma unroll
            for (int mi = 0; mi < 4; mi++)
#pragma unroll
                for (int ni = 0; ni < 4; ni++)
                    mma_tf32(acc[mi][ni], af[mi], bf[ni]);
        }

        __syncthreads();
        if (has_next) {
            STS_TILES();
            __syncthreads();
        }
    }

#pragma unroll
    for (int mi = 0; mi < 4; mi++) {
#pragma unroll
        for (int ni = 0; ni < 4; ni++) {
            const int row = m0 + wm + mi * 16 + gid;
            const int col = n0 + wn + ni * 8 + (gtd << 1);
            const float b0 = bias[col];
            const float b1 = bias[col + 1];
            float2 v0, v1;
            v0.x = acc[mi][ni][0] + b0; v0.y = acc[mi][ni][1] + b1;
            v1.x = acc[mi][ni][2] + b0; v1.y = acc[mi][ni][3] + b1;
            *(float2*)(C + (size_t)row * N + col)       = v0;
            *(float2*)(C + (size_t)(row + 8) * N + col) = v1;
        }
    }
#undef LDG_TILES
#undef STS_TILES
}

// ---------------------------------------------------------------------------
// Flash attention, causal, TF32 tensor-core.
// grid: (T/64, B*H). 128 threads = 4 warps, each warp owns 16 q rows.
// Q fragments live in registers (pre-scaled by 1/8, tf32).
// K, V in natural row-major smem; strides chosen for conflict-free frag LDS.
// P redistributed accumulator->A-fragment via shuffles (no smem round trip).
// ---------------------------------------------------------------------------
__global__ __launch_bounds__(128) void attn_mma(
    const float* __restrict__ qkv, float* __restrict__ att)
{
    __shared__ float Ks[64][68];   // [c][d]  bank(B-frag) = gid*4+gtd  (distinct)
    __shared__ float Vs[64][72];   // [c][d]  bank(B-frag) = gtd*8+gid  (distinct)

    const int qb = blockIdx.x;
    const int b  = blockIdx.y >> 4;
    const int h  = blockIdx.y & 15;

    const int tid  = threadIdx.x;
    const int lane = tid & 31;
    const int warp = tid >> 5;
    const int gid  = lane >> 2;
    const int gtd  = lane & 3;
    const int wq   = warp * 16;

    // Q fragments in registers, scaled by 1/sqrt(64)=0.125 (exact), tf32.
    uint32_t qf[8][4];
    {
        const float* qp = qkv + (size_t)(b * SEQ + qb * 64) * C3 + h * HEADD;
        const int r0 = wq + gid, r1 = r0 + 8;
#pragma unroll
        for (int ks = 0; ks < 8; ks++) {
            const int c = ks * 8 + gtd;
            qf[ks][0] = to_tf32u(qp[(size_t)r0 * C3 + c] * 0.125f);
            qf[ks][1] = to_tf32u(qp[(size_t)r1 * C3 + c] * 0.125f);
            qf[ks][2] = to_tf32u(qp[(size_t)r0 * C3 + c + 4] * 0.125f);
            qf[ks][3] = to_tf32u(qp[(size_t)r1 * C3 + c + 4] * 0.125f);
        }
    }

    float m0 = -1e30f, m1 = -1e30f, l0 = 0.f, l1 = 0.f;
    float o[8][4];
#pragma unroll
    for (int dt = 0; dt < 8; dt++)
#pragma unroll
        for (int r = 0; r < 4; r++) o[dt][r] = 0.f;

    for (int jb = 0; jb <= qb; jb++) {
        const float* kp = qkv + (size_t)(b * SEQ + jb * 64) * C3 + N_EMBD + h * HEADD;
        const float* vp = kp + N_EMBD;

        __syncthreads();   // prev iteration's smem reads done
        for (int i = tid; i < 1024; i += 128) {
            const int r = i >> 4, c4 = (i & 15) << 2;
            float4 kv = *(const float4*)(kp + (size_t)r * C3 + c4);
            Ks[r][c4 + 0] = to_tf32(kv.x); Ks[r][c4 + 1] = to_tf32(kv.y);
            Ks[r][c4 + 2] = to_tf32(kv.z); Ks[r][c4 + 3] = to_tf32(kv.w);
            float4 vv = *(const float4*)(vp + (size_t)r * C3 + c4);
            Vs[r][c4 + 0] = to_tf32(vv.x); Vs[r][c4 + 1] = to_tf32(vv.y);
            Vs[r][c4 + 2] = to_tf32(vv.z); Vs[r][c4 + 3] = to_tf32(vv.w);
        }
        __syncthreads();

        // S = (Q/8) K^T  — 8 n-tiles of 8 cols, 8 k-steps over d
        float s[8][4];
#pragma unroll
        for (int nt = 0; nt < 8; nt++)
#pragma unroll
            for (int r = 0; r < 4; r++) s[nt][r] = 0.f;

#pragma unroll
        for (int ks = 0; ks < 8; ks++) {
            const int kr = ks * 8 + gtd;
#pragma unroll
            for (int nt = 0; nt < 8; nt++) {
                uint32_t bf[2];
                bf[0] = __float_as_uint(Ks[nt * 8 + gid][kr]);
                bf[1] = __float_as_uint(Ks[nt * 8 + gid][kr + 4]);
                mma_tf32(s[nt], qf[ks], bf);
            }
        }

        // causal mask on diagonal block
        if (jb == qb) {
            const int r0 = wq + gid, r1 = r0 + 8;
#pragma unroll
            for (int nt = 0; nt < 8; nt++) {
                const int c = nt * 8 + gtd * 2;
                if (c     > r0) s[nt][0] = -1e30f;
                if (c + 1 > r0) s[nt][1] = -1e30f;
                if (c     > r1) s[nt][2] = -1e30f;
                if (c + 1 > r1) s[nt][3] = -1e30f;
            }
        }

        // online softmax (rows: r0 -> regs 0,1 ; r1 -> regs 2,3)
        float mx0 = -1e30f, mx1 = -1e30f;
#pragma unroll
        for (int nt = 0; nt < 8; nt++) {
            mx0 = fmaxf(mx0, fmaxf(s[nt][0], s[nt][1]));
            mx1 = fmaxf(mx1, fmaxf(s[nt][2], s[nt][3]));
        }
        mx0 = fmaxf(mx0, __shfl_xor_sync(0xffffffffu, mx0, 1));
        mx0 = fmaxf(mx0, __shfl_xor_sync(0xffffffffu, mx0, 2));
        mx1 = fmaxf(mx1, __shfl_xor_sync(0xffffffffu, mx1, 1));
        mx1 = fmaxf(mx1, __shfl_xor_sync(0xffffffffu, mx1, 2));

        const float mn0 = fmaxf(m0, mx0), mn1 = fmaxf(m1, mx1);
        const float a0 = __expf(m0 - mn0), a1 = __expf(m1 - mn1);
        m0 = mn0; m1 = mn1;

        float rs0 = 0.f, rs1 = 0.f;
        uint32_t p[8][4];
#pragma unroll
        for (int nt = 0; nt < 8; nt++) {
            float p0 = __expf(s[nt][0] - mn0);
            float p1 = __expf(s[nt][1] - mn0);
            float p2 = __expf(s[nt][2] - mn1);
            float p3 = __expf(s[nt][3] - mn1);
            rs0 += p0 + p1; rs1 += p2 + p3;
            p[nt][0] = to_tf32u(p0); p[nt][1] = to_tf32u(p1);
            p[nt][2] = to_tf32u(p2); p[nt][3] = to_tf32u(p3);
        }
        rs0 += __shfl_xor_sync(0xffffffffu, rs0, 1);
        rs0 += __shfl_xor_sync(0xffffffffu, rs0, 2);
        rs1 += __shfl_xor_sync(0xffffffffu, rs1, 1);
        rs1 += __shfl_xor_sync(0xffffffffu, rs1, 2);
        l0 = l0 * a0 + rs0;
        l1 = l1 * a1 + rs1;

#pragma unroll
        for (int dt = 0; dt < 8; dt++) {
            o[dt][0] *= a0; o[dt][1] *= a0;
            o[dt][2] *= a1; o[dt][3] *= a1;
        }

        // O += P V : redistribute P acc-layout -> A-fragment via shuffles
        const int srcA = (lane & ~3) | (gtd >> 1);
        const int srcB = srcA + 2;
        const bool odd = gtd & 1;
#pragma unroll
        for (int cb = 0; cb < 8; cb++) {
            uint32_t e0a = __shfl_sync(0xffffffffu, p[cb][0], srcA);
            uint32_t e1a = __shfl_sync(0xffffffffu, p[cb][1], srcA);
            uint32_t e2a = __shfl_sync(0xffffffffu, p[cb][2], srcA);
            uint32_t e3a = __shfl_sync(0xffffffffu, p[cb][3], srcA);
            uint32_t e0b = __shfl_sync(0xffffffffu, p[cb][0], srcB);
            uint32_t e1b = __shfl_sync(0xffffffffu, p[cb][1], srcB);
            uint32_t e2b = __shfl_sync(0xffffffffu, p[cb][2], srcB);
            uint32_t e3b = __shfl_sync(0xffffffffu, p[cb][3], srcB);
            uint32_t af[4];
            af[0] = odd ? e1a : e0a;
            af[1] = odd ? e3a : e2a;
            af[2] = odd ? e1b : e0b;
            af[3] = odd ? e3b : e2b;
            const int kr = cb * 8 + gtd;
#pragma unroll
            for (int dt = 0; dt < 8; dt++) {
                uint32_t bf[2];
                bf[0] = __float_as_uint(Vs[kr][dt * 8 + gid]);
                bf[1] = __float_as_uint(Vs[kr + 4][dt * 8 + gid]);
                mma_tf32(o[dt], af, bf);
            }
        }
    }

    // normalize and write out
    const float inv0 = 1.f / l0, inv1 = 1.f / l1;
    const size_t grow0 = (size_t)(b * SEQ + qb * 64 + wq + gid);
    const int colb = h * HEADD + gtd * 2;
#pragma unroll
    for (int dt = 0; dt < 8; dt++) {
        float2 v0, v1;
        v0.x = o[dt][0] * inv0; v0.y = o[dt][1] * inv0;
        v1.x = o[dt][2] * inv1; v1.y = o[dt][3] * inv1;
        *(float2*)(att + grow0 * N_EMBD + colb + dt * 8)       = v0;
        *(float2*)(att + (grow0 + 8) * N_EMBD + colb + dt * 8) = v1;
    }
}

// ---------------------------------------------------------------------------
extern "C" void kernel_launch(void* const* d_in, const int* in_sizes, int n_in,
                              void* d_out, int out_size)
{
    const float* x     = (const float*)d_in[0];
    const float* W_qkv = (const float*)d_in[1];
    const float* b_qkv = (const float*)d_in[2];
    const float* W_out = (const float*)d_in[3];
    const float* b_out = (const float*)d_in[4];
    float* out = (float*)d_out;

    float* qkv; float* att;
    cudaGetSymbolAddress((void**)&qkv, g_qkv);
    cudaGetSymbolAddress((void**)&att, g_att);

    // 1) qkv = x @ W_qkv + b_qkv   [8192,3072]
    gemm_tf32<<<dim3(C3 / 128, ROWS / 128), 256>>>(x, W_qkv, b_qkv, qkv,
                                                   ROWS, C3, N_EMBD);
    // 2) attention -> g_att [8192,1024]
    attn_mma<<<dim3(SEQ / 64, BATCH * N_HEAD), 128>>>(qkv, att);
    // 3) out = att @ W_out + b_out
    gemm_tf32<<<dim3(N_EMBD / 128, ROWS / 128), 256>>>(att, W_out, b_out, out,
                                                       ROWS, N_EMBD, N_EMBD);
}

// round 5
// speedup vs baseline: 3.5954x; 1.2028x over previous
#include <cuda_runtime.h>
#include <cstdint>
#include <math.h>

#define N_EMBD 1024
#define N_HEAD 16
#define HEADD  64
#define BATCH  4
#define SEQ    2048
#define ROWS   (BATCH * SEQ)          // 8192
#define C3     (3 * N_EMBD)           // 3072

// scratch (allocation-free rule: device globals)
__device__ float g_qkv[(size_t)ROWS * C3];        // [8192, 3072]
__device__ float g_att[(size_t)ROWS * N_EMBD];    // [8192, 1024]
__device__ float g_xr [(size_t)ROWS * N_EMBD];    // tf32-rounded x
__device__ float g_wqr[(size_t)N_EMBD * C3];      // tf32-rounded W_qkv
__device__ float g_wor[(size_t)N_EMBD * N_EMBD];  // tf32-rounded W_out

// ---------------------------------------------------------------------------
__device__ __forceinline__ float to_tf32(float x) {
    uint32_t o;
    asm("cvt.rna.tf32.f32 %0, %1;" : "=r"(o) : "f"(x));
    return __uint_as_float(o);
}
__device__ __forceinline__ uint32_t to_tf32u(float x) {
    uint32_t o;
    asm("cvt.rna.tf32.f32 %0, %1;" : "=r"(o) : "f"(x));
    return o;
}
__device__ __forceinline__ uint32_t smem_u32(const void* p) {
    uint32_t a;
    asm("{ .reg .u64 t; cvta.to.shared.u64 t, %1; cvt.u32.u64 %0, t; }" : "=r"(a) : "l"(p));
    return a;
}
__device__ __forceinline__ void cp_async16(uint32_t dst, const float* src) {
    asm volatile("cp.async.cg.shared.global [%0], [%1], 16;" :: "r"(dst), "l"(src));
}
#define CP_COMMIT() asm volatile("cp.async.commit_group;" ::: "memory")
#define CP_WAIT(n)  asm volatile("cp.async.wait_group %0;" :: "n"(n) : "memory")

__device__ __forceinline__ void mma_tf32(float* d, const uint32_t* a, const uint32_t* b) {
    asm volatile(
        "mma.sync.aligned.m16n8k8.row.col.f32.tf32.tf32.f32 "
        "{%0,%1,%2,%3}, {%4,%5,%6,%7}, {%8,%9}, {%0,%1,%2,%3};"
        : "+f"(d[0]), "+f"(d[1]), "+f"(d[2]), "+f"(d[3])
        : "r"(a[0]), "r"(a[1]), "r"(a[2]), "r"(a[3]), "r"(b[0]), "r"(b[1]));
}

// ---------------------------------------------------------------------------
// pre-pass: tf32 (rna) rounding, vectorized
// ---------------------------------------------------------------------------
__global__ __launch_bounds__(256) void round_rna(const float* __restrict__ in,
                                                 float* __restrict__ out) {
    int i = blockIdx.x * 256 + threadIdx.x;
    float4 v = ((const float4*)in)[i];
    v.x = to_tf32(v.x); v.y = to_tf32(v.y);
    v.z = to_tf32(v.z); v.w = to_tf32(v.w);
    ((float4*)out)[i] = v;
}

// ---------------------------------------------------------------------------
// TF32 mma.sync GEMM + bias: C[M,N] = A[M,K=1024] @ B[1024,N] + bias[N]
// 128x128 tile, BK=32, 256 threads = 8 warps, cp.async double-buffered smem.
// Inputs must already be tf32-rounded (cp.async copies raw bits).
// __launch_bounds__(256,2) -> <=128 regs -> 2 CTAs/SM.
// ---------------------------------------------------------------------------
#define AS_STRIDE 36      // floats per A row  (144 B)
#define BS_STRIDE 136     // floats per B row  (544 B)
#define A_STAGE   (128 * AS_STRIDE * 4)   // 18432 B
#define B_STAGE   (32 * BS_STRIDE * 4)    // 17408 B
#define GEMM_SMEM (2 * A_STAGE + 2 * B_STAGE)  // 71680 B

__global__ __launch_bounds__(256, 2) void gemm_tf32(
    const float* __restrict__ A, const float* __restrict__ B,
    const float* __restrict__ bias, float* __restrict__ C,
    int M, int N, int K)
{
    extern __shared__ char smem[];
    const uint32_t sb = smem_u32(smem);

    const int tid  = threadIdx.x;
    const int lane = tid & 31;
    const int warp = tid >> 5;
    const int wm   = (warp >> 2) * 64;
    const int wn   = (warp & 3) * 32;

    const int m0 = blockIdx.y * 128;
    const int n0 = blockIdx.x * 128;

    const int gid = lane >> 2;
    const int gtd = lane & 3;

    float acc[4][4][4];
#pragma unroll
    for (int mi = 0; mi < 4; mi++)
#pragma unroll
        for (int ni = 0; ni < 4; ni++)
#pragma unroll
            for (int r = 0; r < 4; r++) acc[mi][ni][r] = 0.f;

    // per-thread load coordinates (4 float4 for A, 4 for B per stage)
    // A slots: s = tid + i*256 : row = s>>1 (two 16B pieces/row), kc = (s&1)*4? -> need 8 pieces/row
    //   A tile: 128 rows x 32 k = 128x8 float4 slots (1024). s: row=s>>3, kc=(s&7)*4
    //   B tile: 32 k x 128 n  = 32x32 float4 slots (1024). s: kr=s>>5, nc=(s&31)*4

#define PREFETCH(c, buf)                                                       \
    {                                                                          \
        const float* Ag = A + (size_t)m0 * K + (c) * 32;                       \
        const float* Bg = B + (size_t)((c) * 32) * N + n0;                     \
        const uint32_t sA = sb + (buf) * A_STAGE;                              \
        const uint32_t sB = sb + 2 * A_STAGE + (buf) * B_STAGE;                \
        _Pragma("unroll")                                                      \
        for (int i = 0; i < 4; i++) {                                          \
            int s  = tid + i * 256;                                            \
            int ar = s >> 3, akc = (s & 7) << 2;                               \
            cp_async16(sA + (ar * AS_STRIDE + akc) * 4,                        \
                       Ag + (size_t)ar * K + akc);                             \
            int bkr = s >> 5, bnc = (s & 31) << 2;                             \
            cp_async16(sB + (bkr * BS_STRIDE + bnc) * 4,                       \
                       Bg + (size_t)bkr * N + bnc);                            \
        }                                                                      \
        CP_COMMIT();                                                           \
    }

    const int NK = K >> 5;   // 32 chunks
    PREFETCH(0, 0);
    PREFETCH(1, 1);

    for (int c = 0; c < NK; c++) {
        if (c + 1 < NK) CP_WAIT(1); else CP_WAIT(0);
        __syncthreads();

        const float* As = (const float*)(smem + (c & 1) * A_STAGE);
        const float* Bs = (const float*)(smem + 2 * A_STAGE + (c & 1) * B_STAGE);

#pragma unroll
        for (int kk = 0; kk < 4; kk++) {
            const int kb = kk * 8;
            uint32_t af[4][4];
#pragma unroll
            for (int mi = 0; mi < 4; mi++) {
                const int mr = wm + mi * 16 + gid;
                const int kc = kb + gtd;
                af[mi][0] = __float_as_uint(As[mr * AS_STRIDE + kc]);
                af[mi][1] = __float_as_uint(As[(mr + 8) * AS_STRIDE + kc]);
                af[mi][2] = __float_as_uint(As[mr * AS_STRIDE + kc + 4]);
                af[mi][3] = __float_as_uint(As[(mr + 8) * AS_STRIDE + kc + 4]);
            }
            uint32_t bf[4][2];
#pragma unroll
            for (int ni = 0; ni < 4; ni++) {
                const int nc = wn + ni * 8 + gid;
                const int kr = kb + gtd;
                bf[ni][0] = __float_as_uint(Bs[kr * BS_STRIDE + nc]);
                bf[ni][1] = __float_as_uint(Bs[(kr + 4) * BS_STRIDE + nc]);
            }
#pragma unroll
            for (int mi = 0; mi < 4; mi++)
#pragma unroll
                for (int ni = 0; ni < 4; ni++)
                    mma_tf32(acc[mi][ni], af[mi], bf[ni]);
        }

        __syncthreads();
        if (c + 2 < NK) PREFETCH(c + 2, c & 1);
    }

    // epilogue: fp32 bias add
#pragma unroll
    for (int mi = 0; mi < 4; mi++) {
#pragma unroll
        for (int ni = 0; ni < 4; ni++) {
            const int row = m0 + wm + mi * 16 + gid;
            const int col = n0 + wn + ni * 8 + (gtd << 1);
            const float b0 = bias[col];
            const float b1 = bias[col + 1];
            float2 v0, v1;
            v0.x = acc[mi][ni][0] + b0; v0.y = acc[mi][ni][1] + b1;
            v1.x = acc[mi][ni][2] + b0; v1.y = acc[mi][ni][3] + b1;
            *(float2*)(C + (size_t)row * N + col)       = v0;
            *(float2*)(C + (size_t)(row + 8) * N + col) = v1;
        }
    }
#undef PREFETCH
}

// ---------------------------------------------------------------------------
// Flash attention, causal, TF32 mma.sync (round-3 kernel; output tf32-rounded)
// ---------------------------------------------------------------------------
__global__ __launch_bounds__(128) void attn_mma(
    const float* __restrict__ qkv, float* __restrict__ att)
{
    __shared__ float Ks[64][68];
    __shared__ float Vs[64][72];

    const int qb = blockIdx.x;
    const int b  = blockIdx.y >> 4;
    const int h  = blockIdx.y & 15;

    const int tid  = threadIdx.x;
    const int lane = tid & 31;
    const int warp = tid >> 5;
    const int gid  = lane >> 2;
    const int gtd  = lane & 3;
    const int wq   = warp * 16;

    uint32_t qf[8][4];
    {
        const float* qp = qkv + (size_t)(b * SEQ + qb * 64) * C3 + h * HEADD;
        const int r0 = wq + gid, r1 = r0 + 8;
#pragma unroll
        for (int ks = 0; ks < 8; ks++) {
            const int c = ks * 8 + gtd;
            qf[ks][0] = to_tf32u(qp[(size_t)r0 * C3 + c] * 0.125f);
            qf[ks][1] = to_tf32u(qp[(size_t)r1 * C3 + c] * 0.125f);
            qf[ks][2] = to_tf32u(qp[(size_t)r0 * C3 + c + 4] * 0.125f);
            qf[ks][3] = to_tf32u(qp[(size_t)r1 * C3 + c + 4] * 0.125f);
        }
    }

    float m0 = -1e30f, m1 = -1e30f, l0 = 0.f, l1 = 0.f;
    float o[8][4];
#pragma unroll
    for (int dt = 0; dt < 8; dt++)
#pragma unroll
        for (int r = 0; r < 4; r++) o[dt][r] = 0.f;

    for (int jb = 0; jb <= qb; jb++) {
        const float* kp = qkv + (size_t)(b * SEQ + jb * 64) * C3 + N_EMBD + h * HEADD;
        const float* vp = kp + N_EMBD;

        __syncthreads();
        for (int i = tid; i < 1024; i += 128) {
            const int r = i >> 4, c4 = (i & 15) << 2;
            float4 kv = *(const float4*)(kp + (size_t)r * C3 + c4);
            Ks[r][c4 + 0] = to_tf32(kv.x); Ks[r][c4 + 1] = to_tf32(kv.y);
            Ks[r][c4 + 2] = to_tf32(kv.z); Ks[r][c4 + 3] = to_tf32(kv.w);
            float4 vv = *(const float4*)(vp + (size_t)r * C3 + c4);
            Vs[r][c4 + 0] = to_tf32(vv.x); Vs[r][c4 + 1] = to_tf32(vv.y);
            Vs[r][c4 + 2] = to_tf32(vv.z); Vs[r][c4 + 3] = to_tf32(vv.w);
        }
        __syncthreads();

        float s[8][4];
#pragma unroll
        for (int nt = 0; nt < 8; nt++)
#pragma unroll
            for (int r = 0; r < 4; r++) s[nt][r] = 0.f;

#pragma unroll
        for (int ks = 0; ks < 8; ks++) {
            const int kr = ks * 8 + gtd;
#pragma unroll
            for (int nt = 0; nt < 8; nt++) {
                uint32_t bf[2];
                bf[0] = __float_as_uint(Ks[nt * 8 + gid][kr]);
                bf[1] = __float_as_uint(Ks[nt * 8 + gid][kr + 4]);
                mma_tf32(s[nt], qf[ks], bf);
            }
        }

        if (jb == qb) {
            const int r0 = wq + gid, r1 = r0 + 8;
#pragma unroll
            for (int nt = 0; nt < 8; nt++) {
                const int c = nt * 8 + gtd * 2;
                if (c     > r0) s[nt][0] = -1e30f;
                if (c + 1 > r0) s[nt][1] = -1e30f;
                if (c     > r1) s[nt][2] = -1e30f;
                if (c + 1 > r1) s[nt][3] = -1e30f;
            }
        }

        float mx0 = -1e30f, mx1 = -1e30f;
#pragma unroll
        for (int nt = 0; nt < 8; nt++) {
            mx0 = fmaxf(mx0, fmaxf(s[nt][0], s[nt][1]));
            mx1 = fmaxf(mx1, fmaxf(s[nt][2], s[nt][3]));
        }
        mx0 = fmaxf(mx0, __shfl_xor_sync(0xffffffffu, mx0, 1));
        mx0 = fmaxf(mx0, __shfl_xor_sync(0xffffffffu, mx0, 2));
        mx1 = fmaxf(mx1, __shfl_xor_sync(0xffffffffu, mx1, 1));
        mx1 = fmaxf(mx1, __shfl_xor_sync(0xffffffffu, mx1, 2));

        const float mn0 = fmaxf(m0, mx0), mn1 = fmaxf(m1, mx1);
        const float a0 = __expf(m0 - mn0), a1 = __expf(m1 - mn1);
        m0 = mn0; m1 = mn1;

        float rs0 = 0.f, rs1 = 0.f;
        uint32_t p[8][4];
#pragma unroll
        for (int nt = 0; nt < 8; nt++) {
            float p0 = __expf(s[nt][0] - mn0);
            float p1 = __expf(s[nt][1] - mn0);
            float p2 = __expf(s[nt][2] - mn1);
            float p3 = __expf(s[nt][3] - mn1);
            rs0 += p0 + p1; rs1 += p2 + p3;
            p[nt][0] = to_tf32u(p0); p[nt][1] = to_tf32u(p1);
            p[nt][2] = to_tf32u(p2); p[nt][3] = to_tf32u(p3);
        }
        rs0 += __shfl_xor_sync(0xffffffffu, rs0, 1);
        rs0 += __shfl_xor_sync(0xffffffffu, rs0, 2);
        rs1 += __shfl_xor_sync(0xffffffffu, rs1, 1);
        rs1 += __shfl_xor_sync(0xffffffffu, rs1, 2);
        l0 = l0 * a0 + rs0;
        l1 = l1 * a1 + rs1;

#pragma unroll
        for (int dt = 0; dt < 8; dt++) {
            o[dt][0] *= a0; o[dt][1] *= a0;
            o[dt][2] *= a1; o[dt][3] *= a1;
        }

        const int srcA = (lane & ~3) | (gtd >> 1);
        const int srcB = srcA + 2;
        const bool odd = gtd & 1;
#pragma unroll
        for (int cb = 0; cb < 8; cb++) {
            uint32_t e0a = __shfl_sync(0xffffffffu, p[cb][0], srcA);
            uint32_t e1a = __shfl_sync(0xffffffffu, p[cb][1], srcA);
            uint32_t e2a = __shfl_sync(0xffffffffu, p[cb][2], srcA);
            uint32_t e3a = __shfl_sync(0xffffffffu, p[cb][3], srcA);
            uint32_t e0b = __shfl_sync(0xffffffffu, p[cb][0], srcB);
            uint32_t e1b = __shfl_sync(0xffffffffu, p[cb][1], srcB);
            uint32_t e2b = __shfl_sync(0xffffffffu, p[cb][2], srcB);
            uint32_t e3b = __shfl_sync(0xffffffffu, p[cb][3], srcB);
            uint32_t af[4];
            af[0] = odd ? e1a : e0a;
            af[1] = odd ? e3a : e2a;
            af[2] = odd ? e1b : e0b;
            af[3] = odd ? e3b : e2b;
            const int kr = cb * 8 + gtd;
#pragma unroll
            for (int dt = 0; dt < 8; dt++) {
                uint32_t bf[2];
                bf[0] = __float_as_uint(Vs[kr][dt * 8 + gid]);
                bf[1] = __float_as_uint(Vs[kr + 4][dt * 8 + gid]);
                mma_tf32(o[dt], af, bf);
            }
        }
    }

    // normalize, round to tf32 (gemm2 consumes raw bits via cp.async), write
    const float inv0 = 1.f / l0, inv1 = 1.f / l1;
    const size_t grow0 = (size_t)(b * SEQ + qb * 64 + wq + gid);
    const int colb = h * HEADD + gtd * 2;
#pragma unroll
    for (int dt = 0; dt < 8; dt++) {
        float2 v0, v1;
        v0.x = to_tf32(o[dt][0] * inv0); v0.y = to_tf32(o[dt][1] * inv0);
        v1.x = to_tf32(o[dt][2] * inv1); v1.y = to_tf32(o[dt][3] * inv1);
        *(float2*)(att + grow0 * N_EMBD + colb + dt * 8)       = v0;
        *(float2*)(att + (grow0 + 8) * N_EMBD + colb + dt * 8) = v1;
    }
}

// ---------------------------------------------------------------------------
extern "C" void kernel_launch(void* const* d_in, const int* in_sizes, int n_in,
                              void* d_out, int out_size)
{
    const float* x     = (const float*)d_in[0];
    const float* W_qkv = (const float*)d_in[1];
    const float* b_qkv = (const float*)d_in[2];
    const float* W_out = (const float*)d_in[3];
    const float* b_out = (const float*)d_in[4];
    float* out = (float*)d_out;

    float *qkv, *att, *xr, *wqr, *wor;
    cudaGetSymbolAddress((void**)&qkv, g_qkv);
    cudaGetSymbolAddress((void**)&att, g_att);
    cudaGetSymbolAddress((void**)&xr,  g_xr);
    cudaGetSymbolAddress((void**)&wqr, g_wqr);
    cudaGetSymbolAddress((void**)&wor, g_wor);

    cudaFuncSetAttribute(gemm_tf32, cudaFuncAttributeMaxDynamicSharedMemorySize,
                         GEMM_SMEM);

    // pre-pass: tf32 rounding (cp.async copies raw bits into the MMA)
    round_rna<<<ROWS * N_EMBD / 1024, 256>>>(x, xr);
    round_rna<<<(size_t)N_EMBD * C3 / 1024, 256>>>(W_qkv, wqr);
    round_rna<<<(size_t)N_EMBD * N_EMBD / 1024, 256>>>(W_out, wor);

    // 1) qkv = x @ W_qkv + b_qkv
    gemm_tf32<<<dim3(C3 / 128, ROWS / 128), 256, GEMM_SMEM>>>(
        xr, wqr, b_qkv, qkv, ROWS, C3, N_EMBD);
    // 2) attention
    attn_mma<<<dim3(SEQ / 64, BATCH * N_HEAD), 128>>>(qkv, att);
    // 3) out = att @ W_out + b_out
    gemm_tf32<<<dim3(N_EMBD / 128, ROWS / 128), 256, GEMM_SMEM>>>(
        att, wor, b_out, out, ROWS, N_EMBD, N_EMBD);
}

// round 6
// speedup vs baseline: 3.9317x; 1.0935x over previous
#include <cuda_runtime.h>
#include <cstdint>
#include <math.h>

#define N_EMBD 1024
#define N_HEAD 16
#define HEADD  64
#define BATCH  4
#define SEQ    2048
#define ROWS   (BATCH * SEQ)          // 8192
#define C3     (3 * N_EMBD)           // 3072

// scratch (allocation-free rule: device globals)
__device__ float g_qkv[(size_t)ROWS * C3];        // [8192, 3072] (tf32-rounded)
__device__ float g_att[(size_t)ROWS * N_EMBD];    // [8192, 1024] (tf32-rounded)
__device__ float g_xr [(size_t)ROWS * N_EMBD];    // tf32-rounded x
__device__ float g_wqr[(size_t)N_EMBD * C3];      // tf32-rounded W_qkv
__device__ float g_wor[(size_t)N_EMBD * N_EMBD];  // tf32-rounded W_out

// ---------------------------------------------------------------------------
__device__ __forceinline__ float to_tf32(float x) {
    uint32_t o;
    asm("cvt.rna.tf32.f32 %0, %1;" : "=r"(o) : "f"(x));
    return __uint_as_float(o);
}
__device__ __forceinline__ uint32_t to_tf32u(float x) {
    uint32_t o;
    asm("cvt.rna.tf32.f32 %0, %1;" : "=r"(o) : "f"(x));
    return o;
}
__device__ __forceinline__ uint32_t smem_u32(const void* p) {
    uint32_t a;
    asm("{ .reg .u64 t; cvta.to.shared.u64 t, %1; cvt.u32.u64 %0, t; }" : "=r"(a) : "l"(p));
    return a;
}
__device__ __forceinline__ void cp_async16(uint32_t dst, const float* src) {
    asm volatile("cp.async.cg.shared.global [%0], [%1], 16;" :: "r"(dst), "l"(src));
}
#define CP_COMMIT() asm volatile("cp.async.commit_group;" ::: "memory")
#define CP_WAIT(n)  asm volatile("cp.async.wait_group %0;" :: "n"(n) : "memory")

__device__ __forceinline__ void mma_tf32(float* d, const uint32_t* a, const uint32_t* b) {
    asm volatile(
        "mma.sync.aligned.m16n8k8.row.col.f32.tf32.tf32.f32 "
        "{%0,%1,%2,%3}, {%4,%5,%6,%7}, {%8,%9}, {%0,%1,%2,%3};"
        : "+f"(d[0]), "+f"(d[1]), "+f"(d[2]), "+f"(d[3])
        : "r"(a[0]), "r"(a[1]), "r"(a[2]), "r"(a[3]), "r"(b[0]), "r"(b[1]));
}

// ---------------------------------------------------------------------------
// pre-pass: tf32 (rna) rounding, vectorized
// ---------------------------------------------------------------------------
__global__ __launch_bounds__(256) void round_rna(const float* __restrict__ in,
                                                 float* __restrict__ out) {
    int i = blockIdx.x * 256 + threadIdx.x;
    float4 v = ((const float4*)in)[i];
    v.x = to_tf32(v.x); v.y = to_tf32(v.y);
    v.z = to_tf32(v.z); v.w = to_tf32(v.w);
    ((float4*)out)[i] = v;
}

// ---------------------------------------------------------------------------
// TF32 mma.sync GEMM + bias: C[M,N] = A[M,K] @ B[K,N] + bias[N]
// 128x128 tile, BK=32, 256 threads, cp.async 3-stage pipeline, 1 sync/chunk.
// ROUND_OUT: round result to tf32 (for tensors consumed by later MMA stages).
// ---------------------------------------------------------------------------
#define AS_STRIDE 36
#define BS_STRIDE 136
#define A_STAGE   (128 * AS_STRIDE * 4)   // 18432 B
#define B_STAGE   (32 * BS_STRIDE * 4)    // 17408 B
#define GEMM_SMEM (3 * (A_STAGE + B_STAGE))  // 107520 B

template <bool ROUND_OUT>
__global__ __launch_bounds__(256, 2) void gemm_tf32(
    const float* __restrict__ A, const float* __restrict__ B,
    const float* __restrict__ bias, float* __restrict__ C,
    int M, int N, int K)
{
    extern __shared__ char smem[];
    const uint32_t sb = smem_u32(smem);

    const int tid  = threadIdx.x;
    const int lane = tid & 31;
    const int warp = tid >> 5;
    const int wm   = (warp >> 2) * 64;
    const int wn   = (warp & 3) * 32;

    const int m0 = blockIdx.y * 128;
    const int n0 = blockIdx.x * 128;

    const int gid = lane >> 2;
    const int gtd = lane & 3;

    float acc[4][4][4];
#pragma unroll
    for (int mi = 0; mi < 4; mi++)
#pragma unroll
        for (int ni = 0; ni < 4; ni++)
#pragma unroll
            for (int r = 0; r < 4; r++) acc[mi][ni][r] = 0.f;

#define PREFETCH(c, buf)                                                       \
    {                                                                          \
        const float* Ag = A + (size_t)m0 * K + (c) * 32;                       \
        const float* Bg = B + (size_t)((c) * 32) * N + n0;                     \
        const uint32_t sA = sb + (buf) * (A_STAGE + B_STAGE);                  \
        const uint32_t sB = sA + A_STAGE;                                      \
        _Pragma("unroll")                                                      \
        for (int i = 0; i < 4; i++) {                                          \
            int s  = tid + i * 256;                                            \
            int ar = s >> 3, akc = (s & 7) << 2;                               \
            cp_async16(sA + (ar * AS_STRIDE + akc) * 4,                        \
                       Ag + (size_t)ar * K + akc);                             \
            int bkr = s >> 5, bnc = (s & 31) << 2;                             \
            cp_async16(sB + (bkr * BS_STRIDE + bnc) * 4,                       \
                       Bg + (size_t)bkr * N + bnc);                            \
        }                                                                      \
        CP_COMMIT();                                                           \
    }

    const int NK = K >> 5;
    PREFETCH(0, 0);
    PREFETCH(1, 1);

    for (int c = 0; c < NK; c++) {
        if (c + 1 < NK) CP_WAIT(1); else CP_WAIT(0);
        __syncthreads();
        if (c + 2 < NK) PREFETCH(c + 2, (c + 2) % 3);

        const int buf = c % 3;
        const float* As = (const float*)(smem + buf * (A_STAGE + B_STAGE));
        const float* Bs = As + 128 * AS_STRIDE;

#pragma unroll
        for (int kk = 0; kk < 4; kk++) {
            const int kb = kk * 8;
            uint32_t af[4][4];
#pragma unroll
            for (int mi = 0; mi < 4; mi++) {
                const int mr = wm + mi * 16 + gid;
                const int kc = kb + gtd;
                af[mi][0] = __float_as_uint(As[mr * AS_STRIDE + kc]);
                af[mi][1] = __float_as_uint(As[(mr + 8) * AS_STRIDE + kc]);
                af[mi][2] = __float_as_uint(As[mr * AS_STRIDE + kc + 4]);
                af[mi][3] = __float_as_uint(As[(mr + 8) * AS_STRIDE + kc + 4]);
            }
            uint32_t bf[4][2];
#pragma unroll
            for (int ni = 0; ni < 4; ni++) {
                const int nc = wn + ni * 8 + gid;
                const int kr = kb + gtd;
                bf[ni][0] = __float_as_uint(Bs[kr * BS_STRIDE + nc]);
                bf[ni][1] = __float_as_uint(Bs[(kr + 4) * BS_STRIDE + nc]);
            }
#pragma unroll
            for (int mi = 0; mi < 4; mi++)
#pragma unroll
                for (int ni = 0; ni < 4; ni++)
                    mma_tf32(acc[mi][ni], af[mi], bf[ni]);
        }
    }

    // epilogue: fp32 bias add (+ optional tf32 rounding for MMA consumers)
#pragma unroll
    for (int mi = 0; mi < 4; mi++) {
#pragma unroll
        for (int ni = 0; ni < 4; ni++) {
            const int row = m0 + wm + mi * 16 + gid;
            const int col = n0 + wn + ni * 8 + (gtd << 1);
            const float b0 = bias[col];
            const float b1 = bias[col + 1];
            float2 v0, v1;
            v0.x = acc[mi][ni][0] + b0; v0.y = acc[mi][ni][1] + b1;
            v1.x = acc[mi][ni][2] + b0; v1.y = acc[mi][ni][3] + b1;
            if (ROUND_OUT) {
                v0.x = to_tf32(v0.x); v0.y = to_tf32(v0.y);
                v1.x = to_tf32(v1.x); v1.y = to_tf32(v1.y);
            }
            *(float2*)(C + (size_t)row * N + col)       = v0;
            *(float2*)(C + (size_t)(row + 8) * N + col) = v1;
        }
    }
#undef PREFETCH
}

// ---------------------------------------------------------------------------
// Flash attention, causal, TF32 mma.sync, cp.async double-buffered K/V.
// qkv must be tf32-rounded already (gemm1 epilogue does it).
// grid: (T/64, B*H), 128 threads = 4 warps x 16 q-rows.
// smem layout (floats): [K0:64x68][V0:64x72][K1:64x68][V1:64x72]
// ---------------------------------------------------------------------------
#define KS_STRIDE 68
#define VS_STRIDE 72
#define KV_BUF    (64 * (KS_STRIDE + VS_STRIDE))      // floats per buffer
#define ATTN_SMEM (2 * KV_BUF * 4)                    // 71680 B

__global__ __launch_bounds__(128) void attn_mma(
    const float* __restrict__ qkv, float* __restrict__ att)
{
    extern __shared__ char smem[];
    float* sm = (float*)smem;
    const uint32_t sb = smem_u32(smem);

    const int qb = blockIdx.x;
    const int b  = blockIdx.y >> 4;
    const int h  = blockIdx.y & 15;

    const int tid  = threadIdx.x;
    const int lane = tid & 31;
    const int warp = tid >> 5;
    const int gid  = lane >> 2;
    const int gtd  = lane & 3;
    const int wq   = warp * 16;

    const float* kvbase = qkv + (size_t)(b * SEQ) * C3 + N_EMBD + h * HEADD;

    // prefetch K/V block 0 into buffer 0 (16 pieces of 16B per thread)
#define PREFETCH_KV(jb, buf)                                                   \
    {                                                                          \
        const float* kp = kvbase + (size_t)((jb) * 64) * C3;                   \
        const uint32_t sK = sb + (buf) * (KV_BUF * 4);                         \
        const uint32_t sV = sK + 64 * KS_STRIDE * 4;                           \
        _Pragma("unroll")                                                      \
        for (int i = 0; i < 8; i++) {                                          \
            int s = tid + i * 128;                                             \
            int r = s >> 4, c4 = (s & 15) << 2;                                \
            cp_async16(sK + (r * KS_STRIDE + c4) * 4,                          \
                       kp + (size_t)r * C3 + c4);                              \
            cp_async16(sV + (r * VS_STRIDE + c4) * 4,                          \
                       kp + (size_t)r * C3 + N_EMBD + c4);                     \
        }                                                                      \
        CP_COMMIT();                                                           \
    }

    PREFETCH_KV(0, 0);

    // Q fragments in registers, scaled by 0.125 (exact on tf32 values)
    uint32_t qf[8][4];
    {
        const float* qp = qkv + (size_t)(b * SEQ + qb * 64) * C3 + h * HEADD;
        const int r0 = wq + gid, r1 = r0 + 8;
#pragma unroll
        for (int ks = 0; ks < 8; ks++) {
            const int c = ks * 8 + gtd;
            qf[ks][0] = __float_as_uint(qp[(size_t)r0 * C3 + c] * 0.125f);
            qf[ks][1] = __float_as_uint(qp[(size_t)r1 * C3 + c] * 0.125f);
            qf[ks][2] = __float_as_uint(qp[(size_t)r0 * C3 + c + 4] * 0.125f);
            qf[ks][3] = __float_as_uint(qp[(size_t)r1 * C3 + c + 4] * 0.125f);
        }
    }

    float m0 = -1e30f, m1 = -1e30f, l0 = 0.f, l1 = 0.f;
    float o[8][4];
#pragma unroll
    for (int dt = 0; dt < 8; dt++)
#pragma unroll
        for (int r = 0; r < 4; r++) o[dt][r] = 0.f;

    for (int jb = 0; jb <= qb; jb++) {
        CP_WAIT(0);
        __syncthreads();
        if (jb + 1 <= qb) PREFETCH_KV(jb + 1, (jb + 1) & 1);

        const float* Ks = sm + (jb & 1) * KV_BUF;
        const float* Vs = Ks + 64 * KS_STRIDE;

        // S = (Q/8) K^T
        float s[8][4];
#pragma unroll
        for (int nt = 0; nt < 8; nt++)
#pragma unroll
            for (int r = 0; r < 4; r++) s[nt][r] = 0.f;

#pragma unroll
        for (int ks = 0; ks < 8; ks++) {
            const int kr = ks * 8 + gtd;
#pragma unroll
            for (int nt = 0; nt < 8; nt++) {
                uint32_t bf[2];
                bf[0] = __float_as_uint(Ks[(nt * 8 + gid) * KS_STRIDE + kr]);
                bf[1] = __float_as_uint(Ks[(nt * 8 + gid) * KS_STRIDE + kr + 4]);
                mma_tf32(s[nt], qf[ks], bf);
            }
        }

        if (jb == qb) {
            const int r0 = wq + gid, r1 = r0 + 8;
#pragma unroll
            for (int nt = 0; nt < 8; nt++) {
                const int c = nt * 8 + gtd * 2;
                if (c     > r0) s[nt][0] = -1e30f;
                if (c + 1 > r0) s[nt][1] = -1e30f;
                if (c     > r1) s[nt][2] = -1e30f;
                if (c + 1 > r1) s[nt][3] = -1e30f;
            }
        }

        float mx0 = -1e30f, mx1 = -1e30f;
#pragma unroll
        for (int nt = 0; nt < 8; nt++) {
            mx0 = fmaxf(mx0, fmaxf(s[nt][0], s[nt][1]));
            mx1 = fmaxf(mx1, fmaxf(s[nt][2], s[nt][3]));
        }
        mx0 = fmaxf(mx0, __shfl_xor_sync(0xffffffffu, mx0, 1));
        mx0 = fmaxf(mx0, __shfl_xor_sync(0xffffffffu, mx0, 2));
        mx1 = fmaxf(mx1, __shfl_xor_sync(0xffffffffu, mx1, 1));
        mx1 = fmaxf(mx1, __shfl_xor_sync(0xffffffffu, mx1, 2));

        const float mn0 = fmaxf(m0, mx0), mn1 = fmaxf(m1, mx1);
        const float a0 = __expf(m0 - mn0), a1 = __expf(m1 - mn1);
        m0 = mn0; m1 = mn1;

        float rs0 = 0.f, rs1 = 0.f;
        uint32_t p[8][4];
#pragma unroll
        for (int nt = 0; nt < 8; nt++) {
            float p0 = __expf(s[nt][0] - mn0);
            float p1 = __expf(s[nt][1] - mn0);
            float p2 = __expf(s[nt][2] - mn1);
            float p3 = __expf(s[nt][3] - mn1);
            rs0 += p0 + p1; rs1 += p2 + p3;
            p[nt][0] = to_tf32u(p0); p[nt][1] = to_tf32u(p1);
            p[nt][2] = to_tf32u(p2); p[nt][3] = to_tf32u(p3);
        }
        rs0 += __shfl_xor_sync(0xffffffffu, rs0, 1);
        rs0 += __shfl_xor_sync(0xffffffffu, rs0, 2);
        rs1 += __shfl_xor_sync(0xffffffffu, rs1, 1);
        rs1 += __shfl_xor_sync(0xffffffffu, rs1, 2);
        l0 = l0 * a0 + rs0;
        l1 = l1 * a1 + rs1;

#pragma unroll
        for (int dt = 0; dt < 8; dt++) {
            o[dt][0] *= a0; o[dt][1] *= a0;
            o[dt][2] *= a1; o[dt][3] *= a1;
        }

        // O += P V : P acc-layout -> A-fragment via shuffles
        const int srcA = (lane & ~3) | (gtd >> 1);
        const int srcB = srcA + 2;
        const bool odd = gtd & 1;
#pragma unroll
        for (int cb = 0; cb < 8; cb++) {
            uint32_t e0a = __shfl_sync(0xffffffffu, p[cb][0], srcA);
            uint32_t e1a = __shfl_sync(0xffffffffu, p[cb][1], srcA);
            uint32_t e2a = __shfl_sync(0xffffffffu, p[cb][2], srcA);
            uint32_t e3a = __shfl_sync(0xffffffffu, p[cb][3], srcA);
            uint32_t e0b = __shfl_sync(0xffffffffu, p[cb][0], srcB);
            uint32_t e1b = __shfl_sync(0xffffffffu, p[cb][1], srcB);
            uint32_t e2b = __shfl_sync(0xffffffffu, p[cb][2], srcB);
            uint32_t e3b = __shfl_sync(0xffffffffu, p[cb][3], srcB);
            uint32_t af[4];
            af[0] = odd ? e1a : e0a;
            af[1] = odd ? e3a : e2a;
            af[2] = odd ? e1b : e0b;
            af[3] = odd ? e3b : e2b;
            const int kr = cb * 8 + gtd;
#pragma unroll
            for (int dt = 0; dt < 8; dt++) {
                uint32_t bf[2];
                bf[0] = __float_as_uint(Vs[kr * VS_STRIDE + dt * 8 + gid]);
                bf[1] = __float_as_uint(Vs[(kr + 4) * VS_STRIDE + dt * 8 + gid]);
                mma_tf32(o[dt], af, bf);
            }
        }
    }

    // normalize, round to tf32 (gemm2 consumes raw bits via cp.async), write
    const float inv0 = 1.f / l0, inv1 = 1.f / l1;
    const size_t grow0 = (size_t)(b * SEQ + qb * 64 + wq + gid);
    const int colb = h * HEADD + gtd * 2;
#pragma unroll
    for (int dt = 0; dt < 8; dt++) {
        float2 v0, v1;
        v0.x = to_tf32(o[dt][0] * inv0); v0.y = to_tf32(o[dt][1] * inv0);
        v1.x = to_tf32(o[dt][2] * inv1); v1.y = to_tf32(o[dt][3] * inv1);
        *(float2*)(att + grow0 * N_EMBD + colb + dt * 8)       = v0;
        *(float2*)(att + (grow0 + 8) * N_EMBD + colb + dt * 8) = v1;
    }
#undef PREFETCH_KV
}

// ---------------------------------------------------------------------------
extern "C" void kernel_launch(void* const* d_in, const int* in_sizes, int n_in,
                              void* d_out, int out_size)
{
    const float* x     = (const float*)d_in[0];
    const float* W_qkv = (const float*)d_in[1];
    const float* b_qkv = (const float*)d_in[2];
    const float* W_out = (const float*)d_in[3];
    const float* b_out = (const float*)d_in[4];
    float* out = (float*)d_out;

    float *qkv, *att, *xr, *wqr, *wor;
    cudaGetSymbolAddress((void**)&qkv, g_qkv);
    cudaGetSymbolAddress((void**)&att, g_att);
    cudaGetSymbolAddress((void**)&xr,  g_xr);
    cudaGetSymbolAddress((void**)&wqr, g_wqr);
    cudaGetSymbolAddress((void**)&wor, g_wor);

    cudaFuncSetAttribute(gemm_tf32<true>,
                         cudaFuncAttributeMaxDynamicSharedMemorySize, GEMM_SMEM);
    cudaFuncSetAttribute(gemm_tf32<false>,
                         cudaFuncAttributeMaxDynamicSharedMemorySize, GEMM_SMEM);
    cudaFuncSetAttribute(attn_mma,
                         cudaFuncAttributeMaxDynamicSharedMemorySize, ATTN_SMEM);

    // pre-pass: tf32 rounding (cp.async copies raw bits into the MMA)
    round_rna<<<ROWS * N_EMBD / 1024, 256>>>(x, xr);
    round_rna<<<(size_t)N_EMBD * C3 / 1024, 256>>>(W_qkv, wqr);
    round_rna<<<(size_t)N_EMBD * N_EMBD / 1024, 256>>>(W_out, wor);

    // 1) qkv = x @ W_qkv + b_qkv  (output rounded to tf32 for attention MMA)
    gemm_tf32<true><<<dim3(C3 / 128, ROWS / 128), 256, GEMM_SMEM>>>(
        xr, wqr, b_qkv, qkv, ROWS, C3, N_EMBD);
    // 2) attention
    attn_mma<<<dim3(SEQ / 64, BATCH * N_HEAD), 128, ATTN_SMEM>>>(qkv, att);
    // 3) out = att @ W_out + b_out  (final output stays fp32)
    gemm_tf32<false><<<dim3(N_EMBD / 128, ROWS / 128), 256, GEMM_SMEM>>>(
        att, wor, b_out, out, ROWS, N_EMBD, N_EMBD);
}

// round 7
// speedup vs baseline: 3.9721x; 1.0103x over previous
#include <cuda_runtime.h>
#include <cstdint>
#include <math.h>

#define N_EMBD 1024
#define N_HEAD 16
#define HEADD  64
#define BATCH  4
#define SEQ    2048
#define ROWS   (BATCH * SEQ)          // 8192
#define C3     (3 * N_EMBD)           // 3072

// scratch (allocation-free rule: device globals)
__device__ float g_qkv[(size_t)ROWS * C3];        // [8192, 3072] (tf32-rounded)
__device__ float g_att[(size_t)ROWS * N_EMBD];    // [8192, 1024] (tf32-rounded)
__device__ float g_xr [(size_t)ROWS * N_EMBD];    // tf32-rounded x
__device__ float g_wqt[(size_t)C3 * N_EMBD];      // W_qkv^T [3072,1024], rounded
__device__ float g_wot[(size_t)N_EMBD * N_EMBD];  // W_out^T [1024,1024], rounded

// ---------------------------------------------------------------------------
__device__ __forceinline__ float to_tf32(float x) {
    uint32_t o;
    asm("cvt.rna.tf32.f32 %0, %1;" : "=r"(o) : "f"(x));
    return __uint_as_float(o);
}
__device__ __forceinline__ uint32_t to_tf32u(float x) {
    uint32_t o;
    asm("cvt.rna.tf32.f32 %0, %1;" : "=r"(o) : "f"(x));
    return o;
}
__device__ __forceinline__ uint32_t smem_u32(const void* p) {
    uint32_t a;
    asm("{ .reg .u64 t; cvta.to.shared.u64 t, %1; cvt.u32.u64 %0, t; }" : "=r"(a) : "l"(p));
    return a;
}
__device__ __forceinline__ void cp_async16(uint32_t dst, const float* src) {
    asm volatile("cp.async.cg.shared.global [%0], [%1], 16;" :: "r"(dst), "l"(src));
}
#define CP_COMMIT() asm volatile("cp.async.commit_group;" ::: "memory")
#define CP_WAIT(n)  asm volatile("cp.async.wait_group %0;" :: "n"(n) : "memory")

__device__ __forceinline__ void mma_tf32(float* d, const uint32_t* a, const uint32_t* b) {
    asm volatile(
        "mma.sync.aligned.m16n8k8.row.col.f32.tf32.tf32.f32 "
        "{%0,%1,%2,%3}, {%4,%5,%6,%7}, {%8,%9}, {%0,%1,%2,%3};"
        : "+f"(d[0]), "+f"(d[1]), "+f"(d[2]), "+f"(d[3])
        : "r"(a[0]), "r"(a[1]), "r"(a[2]), "r"(a[3]), "r"(b[0]), "r"(b[1]));
}
__device__ __forceinline__ void ldsm_x4(uint32_t* r, uint32_t addr) {
    asm volatile("ldmatrix.sync.aligned.m8n8.x4.shared.b16 {%0,%1,%2,%3}, [%4];"
                 : "=r"(r[0]), "=r"(r[1]), "=r"(r[2]), "=r"(r[3]) : "r"(addr));
}
__device__ __forceinline__ void ldsm_x2(uint32_t* r, uint32_t addr) {
    asm volatile("ldmatrix.sync.aligned.m8n8.x2.shared.b16 {%0,%1}, [%2];"
                 : "=r"(r[0]), "=r"(r[1]) : "r"(addr));
}

// ---------------------------------------------------------------------------
// pre-pass: tf32 rounding; weight transpose (+rounding)
// ---------------------------------------------------------------------------
__global__ __launch_bounds__(256) void round_rna(const float* __restrict__ in,
                                                 float* __restrict__ out) {
    int i = blockIdx.x * 256 + threadIdx.x;
    float4 v = ((const float4*)in)[i];
    v.x = to_tf32(v.x); v.y = to_tf32(v.y);
    v.z = to_tf32(v.z); v.w = to_tf32(v.w);
    ((float4*)out)[i] = v;
}

// W[1024][N] -> Wt[N][1024], tf32-rounded
__global__ __launch_bounds__(256) void transpose_rna(const float* __restrict__ W,
                                                     float* __restrict__ Wt, int N) {
    __shared__ float t[32][33];
    const int nx = blockIdx.x * 32, ky = blockIdx.y * 32;
    const int tx = threadIdx.x & 31, ty = threadIdx.x >> 5;
#pragma unroll
    for (int i = 0; i < 32; i += 8)
        t[ty + i][tx] = W[(size_t)(ky + ty + i) * N + nx + tx];
    __syncthreads();
#pragma unroll
    for (int i = 0; i < 32; i += 8)
        Wt[(size_t)(nx + ty + i) * 1024 + ky + tx] = to_tf32(t[tx][ty + i]);
}

// ---------------------------------------------------------------------------
// TF32 mma.sync GEMM + bias: C[M,N] = A[M,K] @ Bt[N,K]^T + bias[N]
// Both operands K-major [row][k], 128x128 tile, BK=32, 256 threads.
// ldmatrix fragment loads, cp.async 3-stage pipeline, 1 sync/chunk.
// ---------------------------------------------------------------------------
#define TS_STRIDE 36                            // floats per row (144 B)
#define T_STAGE   (128 * TS_STRIDE * 4)         // 18432 B (A or B tile)
#define GEMM_SMEM (3 * 2 * T_STAGE)             // 110592 B

template <bool ROUND_OUT>
__global__ __launch_bounds__(256, 2) void gemm_tf32(
    const float* __restrict__ A, const float* __restrict__ Bt,
    const float* __restrict__ bias, float* __restrict__ C,
    int M, int N, int K)
{
    extern __shared__ char smem[];
    const uint32_t sb = smem_u32(smem);

    const int tid  = threadIdx.x;
    const int lane = tid & 31;
    const int warp = tid >> 5;
    const int wm   = (warp >> 2) * 64;
    const int wn   = (warp & 3) * 32;

    const int m0 = blockIdx.y * 128;
    const int n0 = blockIdx.x * 128;

    const int gid = lane >> 2;
    const int gtd = lane & 3;

    float acc[4][4][4];
#pragma unroll
    for (int mi = 0; mi < 4; mi++)
#pragma unroll
        for (int ni = 0; ni < 4; ni++)
#pragma unroll
            for (int r = 0; r < 4; r++) acc[mi][ni][r] = 0.f;

    // ldmatrix per-lane address offsets (bytes, within a tile buffer)
    // A x4: row = lane&15 (within 16-row tile), col +4 floats for lanes>=16
    const uint32_t a_off = ((uint32_t)(lane & 15) * TS_STRIDE +
                            ((uint32_t)(lane >> 4) << 2)) * 4;
    // B x2: row = lane&7 (within 8-row tile), col +4 floats for lanes 8-15
    const uint32_t b_off = ((uint32_t)(lane & 7) * TS_STRIDE +
                            (((uint32_t)(lane >> 3) & 1) << 2)) * 4;

#define PREFETCH(c, buf)                                                       \
    {                                                                          \
        const float* Ag = A + (size_t)m0 * K + (c) * 32;                       \
        const float* Bg = Bt + (size_t)n0 * K + (c) * 32;                      \
        const uint32_t sA = sb + (buf) * (2 * T_STAGE);                        \
        const uint32_t sB = sA + T_STAGE;                                      \
        _Pragma("unroll")                                                      \
        for (int i = 0; i < 4; i++) {                                          \
            int s  = tid + i * 256;                                            \
            int r  = s >> 3, kc = (s & 7) << 2;                                \
            cp_async16(sA + (r * TS_STRIDE + kc) * 4,                          \
                       Ag + (size_t)r * K + kc);                               \
            cp_async16(sB + (r * TS_STRIDE + kc) * 4,                          \
                       Bg + (size_t)r * K + kc);                               \
        }                                                                      \
        CP_COMMIT();                                                           \
    }

    const int NK = K >> 5;
    PREFETCH(0, 0);
    PREFETCH(1, 1);

    for (int c = 0; c < NK; c++) {
        if (c + 1 < NK) CP_WAIT(1); else CP_WAIT(0);
        __syncthreads();
        if (c + 2 < NK) PREFETCH(c + 2, (c + 2) % 3);

        const int buf = c % 3;
        const uint32_t sA = sb + buf * (2 * T_STAGE);
        const uint32_t sB = sA + T_STAGE;

#pragma unroll
        for (int kk = 0; kk < 4; kk++) {
            const uint32_t kb4 = (uint32_t)(kk * 8) * 4;   // col offset bytes
            uint32_t af[4][4];
#pragma unroll
            for (int mi = 0; mi < 4; mi++)
                ldsm_x4(af[mi], sA + (uint32_t)(wm + mi * 16) * TS_STRIDE * 4 +
                                 a_off + kb4);
            uint32_t bf[4][2];
#pragma unroll
            for (int ni = 0; ni < 4; ni++)
                ldsm_x2(bf[ni], sB + (uint32_t)(wn + ni * 8) * TS_STRIDE * 4 +
                                 b_off + kb4);
#pragma unroll
            for (int mi = 0; mi < 4; mi++)
#pragma unroll
                for (int ni = 0; ni < 4; ni++)
                    mma_tf32(acc[mi][ni], af[mi], bf[ni]);
        }
    }

    // epilogue: fp32 bias add (+ optional tf32 rounding for MMA consumers)
#pragma unroll
    for (int mi = 0; mi < 4; mi++) {
#pragma unroll
        for (int ni = 0; ni < 4; ni++) {
            const int row = m0 + wm + mi * 16 + gid;
            const int col = n0 + wn + ni * 8 + (gtd << 1);
            const float b0 = bias[col];
            const float b1 = bias[col + 1];
            float2 v0, v1;
            v0.x = acc[mi][ni][0] + b0; v0.y = acc[mi][ni][1] + b1;
            v1.x = acc[mi][ni][2] + b0; v1.y = acc[mi][ni][3] + b1;
            if (ROUND_OUT) {
                v0.x = to_tf32(v0.x); v0.y = to_tf32(v0.y);
                v1.x = to_tf32(v1.x); v1.y = to_tf32(v1.y);
            }
            *(float2*)(C + (size_t)row * N + col)       = v0;
            *(float2*)(C + (size_t)(row + 8) * N + col) = v1;
        }
    }
#undef PREFETCH
}

// ---------------------------------------------------------------------------
// Flash attention, causal, TF32 mma.sync, cp.async double-buffered K/V.
// (unchanged from round 6)
// ---------------------------------------------------------------------------
#define KS_STRIDE 68
#define VS_STRIDE 72
#define KV_BUF    (64 * (KS_STRIDE + VS_STRIDE))
#define ATTN_SMEM (2 * KV_BUF * 4)

__global__ __launch_bounds__(128) void attn_mma(
    const float* __restrict__ qkv, float* __restrict__ att)
{
    extern __shared__ char smem[];
    float* sm = (float*)smem;
    const uint32_t sb = smem_u32(smem);

    const int qb = blockIdx.x;
    const int b  = blockIdx.y >> 4;
    const int h  = blockIdx.y & 15;

    const int tid  = threadIdx.x;
    const int lane = tid & 31;
    const int warp = tid >> 5;
    const int gid  = lane >> 2;
    const int gtd  = lane & 3;
    const int wq   = warp * 16;

    const float* kvbase = qkv + (size_t)(b * SEQ) * C3 + N_EMBD + h * HEADD;

#define PREFETCH_KV(jb, buf)                                                   \
    {                                                                          \
        const float* kp = kvbase + (size_t)((jb) * 64) * C3;                   \
        const uint32_t sK = sb + (buf) * (KV_BUF * 4);                         \
        const uint32_t sV = sK + 64 * KS_STRIDE * 4;                           \
        _Pragma("unroll")                                                      \
        for (int i = 0; i < 8; i++) {                                          \
            int s = tid + i * 128;                                             \
            int r = s >> 4, c4 = (s & 15) << 2;                                \
            cp_async16(sK + (r * KS_STRIDE + c4) * 4,                          \
                       kp + (size_t)r * C3 + c4);                              \
            cp_async16(sV + (r * VS_STRIDE + c4) * 4,                          \
                       kp + (size_t)r * C3 + N_EMBD + c4);                     \
        }                                                                      \
        CP_COMMIT();                                                           \
    }

    PREFETCH_KV(0, 0);

    uint32_t qf[8][4];
    {
        const float* qp = qkv + (size_t)(b * SEQ + qb * 64) * C3 + h * HEADD;
        const int r0 = wq + gid, r1 = r0 + 8;
#pragma unroll
        for (int ks = 0; ks < 8; ks++) {
            const int c = ks * 8 + gtd;
            qf[ks][0] = __float_as_uint(qp[(size_t)r0 * C3 + c] * 0.125f);
            qf[ks][1] = __float_as_uint(qp[(size_t)r1 * C3 + c] * 0.125f);
            qf[ks][2] = __float_as_uint(qp[(size_t)r0 * C3 + c + 4] * 0.125f);
            qf[ks][3] = __float_as_uint(qp[(size_t)r1 * C3 + c + 4] * 0.125f);
        }
    }

    float m0 = -1e30f, m1 = -1e30f, l0 = 0.f, l1 = 0.f;
    float o[8][4];
#pragma unroll
    for (int dt = 0; dt < 8; dt++)
#pragma unroll
        for (int r = 0; r < 4; r++) o[dt][r] = 0.f;

    for (int jb = 0; jb <= qb; jb++) {
        CP_WAIT(0);
        __syncthreads();
        if (jb + 1 <= qb) PREFETCH_KV(jb + 1, (jb + 1) & 1);

        const float* Ks = sm + (jb & 1) * KV_BUF;
        const float* Vs = Ks + 64 * KS_STRIDE;

        float s[8][4];
#pragma unroll
        for (int nt = 0; nt < 8; nt++)
#pragma unroll
            for (int r = 0; r < 4; r++) s[nt][r] = 0.f;

#pragma unroll
        for (int ks = 0; ks < 8; ks++) {
            const int kr = ks * 8 + gtd;
#pragma unroll
            for (int nt = 0; nt < 8; nt++) {
                uint32_t bf[2];
                bf[0] = __float_as_uint(Ks[(nt * 8 + gid) * KS_STRIDE + kr]);
                bf[1] = __float_as_uint(Ks[(nt * 8 + gid) * KS_STRIDE + kr + 4]);
                mma_tf32(s[nt], qf[ks], bf);
            }
        }

        if (jb == qb) {
            const int r0 = wq + gid, r1 = r0 + 8;
#pragma unroll
            for (int nt = 0; nt < 8; nt++) {
                const int c = nt * 8 + gtd * 2;
                if (c     > r0) s[nt][0] = -1e30f;
                if (c + 1 > r0) s[nt][1] = -1e30f;
                if (c     > r1) s[nt][2] = -1e30f;
                if (c + 1 > r1) s[nt][3] = -1e30f;
            }
        }

        float mx0 = -1e30f, mx1 = -1e30f;
#pragma unroll
        for (int nt = 0; nt < 8; nt++) {
            mx0 = fmaxf(mx0, fmaxf(s[nt][0], s[nt][1]));
            mx1 = fmaxf(mx1, fmaxf(s[nt][2], s[nt][3]));
        }
        mx0 = fmaxf(mx0, __shfl_xor_sync(0xffffffffu, mx0, 1));
        mx0 = fmaxf(mx0, __shfl_xor_sync(0xffffffffu, mx0, 2));
        mx1 = fmaxf(mx1, __shfl_xor_sync(0xffffffffu, mx1, 1));
        mx1 = fmaxf(mx1, __shfl_xor_sync(0xffffffffu, mx1, 2));

        const float mn0 = fmaxf(m0, mx0), mn1 = fmaxf(m1, mx1);
        const float a0 = __expf(m0 - mn0), a1 = __expf(m1 - mn1);
        m0 = mn0; m1 = mn1;

        float rs0 = 0.f, rs1 = 0.f;
        uint32_t p[8][4];
#pragma unroll
        for (int nt = 0; nt < 8; nt++) {
            float p0 = __expf(s[nt][0] - mn0);
            float p1 = __expf(s[nt][1] - mn0);
            float p2 = __expf(s[nt][2] - mn1);
            float p3 = __expf(s[nt][3] - mn1);
            rs0 += p0 + p1; rs1 += p2 + p3;
            p[nt][0] = to_tf32u(p0); p[nt][1] = to_tf32u(p1);
            p[nt][2] = to_tf32u(p2); p[nt][3] = to_tf32u(p3);
        }
        rs0 += __shfl_xor_sync(0xffffffffu, rs0, 1);
        rs0 += __shfl_xor_sync(0xffffffffu, rs0, 2);
        rs1 += __shfl_xor_sync(0xffffffffu, rs1, 1);
        rs1 += __shfl_xor_sync(0xffffffffu, rs1, 2);
        l0 = l0 * a0 + rs0;
        l1 = l1 * a1 + rs1;

#pragma unroll
        for (int dt = 0; dt < 8; dt++) {
            o[dt][0] *= a0; o[dt][1] *= a0;
            o[dt][2] *= a1; o[dt][3] *= a1;
        }

        const int srcA = (lane & ~3) | (gtd >> 1);
        const int srcB = srcA + 2;
        const bool odd = gtd & 1;
#pragma unroll
        for (int cb = 0; cb < 8; cb++) {
            uint32_t e0a = __shfl_sync(0xffffffffu, p[cb][0], srcA);
            uint32_t e1a = __shfl_sync(0xffffffffu, p[cb][1], srcA);
            uint32_t e2a = __shfl_sync(0xffffffffu, p[cb][2], srcA);
            uint32_t e3a = __shfl_sync(0xffffffffu, p[cb][3], srcA);
            uint32_t e0b = __shfl_sync(0xffffffffu, p[cb][0], srcB);
            uint32_t e1b = __shfl_sync(0xffffffffu, p[cb][1], srcB);
            uint32_t e2b = __shfl_sync(0xffffffffu, p[cb][2], srcB);
            uint32_t e3b = __shfl_sync(0xffffffffu, p[cb][3], srcB);
            uint32_t af[4];
            af[0] = odd ? e1a : e0a;
            af[1] = odd ? e3a : e2a;
            af[2] = odd ? e1b : e0b;
            af[3] = odd ? e3b : e2b;
            const int kr = cb * 8 + gtd;
#pragma unroll
            for (int dt = 0; dt < 8; dt++) {
                uint32_t bf[2];
                bf[0] = __float_as_uint(Vs[kr * VS_STRIDE + dt * 8 + gid]);
                bf[1] = __float_as_uint(Vs[(kr + 4) * VS_STRIDE + dt * 8 + gid]);
                mma_tf32(o[dt], af, bf);
            }
        }
    }

    const float inv0 = 1.f / l0, inv1 = 1.f / l1;
    const size_t grow0 = (size_t)(b * SEQ + qb * 64 + wq + gid);
    const int colb = h * HEADD + gtd * 2;
#pragma unroll
    for (int dt = 0; dt < 8; dt++) {
        float2 v0, v1;
        v0.x = to_tf32(o[dt][0] * inv0); v0.y = to_tf32(o[dt][1] * inv0);
        v1.x = to_tf32(o[dt][2] * inv1); v1.y = to_tf32(o[dt][3] * inv1);
        *(float2*)(att + grow0 * N_EMBD + colb + dt * 8)       = v0;
        *(float2*)(att + (grow0 + 8) * N_EMBD + colb + dt * 8) = v1;
    }
#undef PREFETCH_KV
}

// ---------------------------------------------------------------------------
extern "C" void kernel_launch(void* const* d_in, const int* in_sizes, int n_in,
                              void* d_out, int out_size)
{
    const float* x     = (const float*)d_in[0];
    const float* W_qkv = (const float*)d_in[1];
    const float* b_qkv = (const float*)d_in[2];
    const float* W_out = (const float*)d_in[3];
    const float* b_out = (const float*)d_in[4];
    float* out = (float*)d_out;

    float *qkv, *att, *xr, *wqt, *wot;
    cudaGetSymbolAddress((void**)&qkv, g_qkv);
    cudaGetSymbolAddress((void**)&att, g_att);
    cudaGetSymbolAddress((void**)&xr,  g_xr);
    cudaGetSymbolAddress((void**)&wqt, g_wqt);
    cudaGetSymbolAddress((void**)&wot, g_wot);

    cudaFuncSetAttribute(gemm_tf32<true>,
                         cudaFuncAttributeMaxDynamicSharedMemorySize, GEMM_SMEM);
    cudaFuncSetAttribute(gemm_tf32<false>,
                         cudaFuncAttributeMaxDynamicSharedMemorySize, GEMM_SMEM);
    cudaFuncSetAttribute(attn_mma,
                         cudaFuncAttributeMaxDynamicSharedMemorySize, ATTN_SMEM);

    // pre-pass: round x; transpose+round weights (Bt layout for ldmatrix)
    round_rna<<<ROWS * N_EMBD / 1024, 256>>>(x, xr);
    transpose_rna<<<dim3(C3 / 32, N_EMBD / 32), 256>>>(W_qkv, wqt, C3);
    transpose_rna<<<dim3(N_EMBD / 32, N_EMBD / 32), 256>>>(W_out, wot, N_EMBD);

    // 1) qkv = x @ W_qkv + b_qkv  (output rounded to tf32 for attention MMA)
    gemm_tf32<true><<<dim3(C3 / 128, ROWS / 128), 256, GEMM_SMEM>>>(
        xr, wqt, b_qkv, qkv, ROWS, C3, N_EMBD);
    // 2) attention
    attn_mma<<<dim3(SEQ / 64, BATCH * N_HEAD), 128, ATTN_SMEM>>>(qkv, att);
    // 3) out = att @ W_out + b_out  (final output stays fp32)
    gemm_tf32<false><<<dim3(N_EMBD / 128, ROWS / 128), 256, GEMM_SMEM>>>(
        att, wot, b_out, out, ROWS, N_EMBD, N_EMBD);
}

// round 8
// speedup vs baseline: 4.1117x; 1.0352x over previous
#include <cuda_runtime.h>
#include <cstdint>
#include <math.h>

#define N_EMBD 1024
#define N_HEAD 16
#define HEADD  64
#define BATCH  4
#define SEQ    2048
#define ROWS   (BATCH * SEQ)          // 8192
#define C3     (3 * N_EMBD)           // 3072

// scratch (allocation-free rule: device globals)
__device__ float g_qkv[(size_t)ROWS * C3];        // [8192, 3072] (tf32-rounded)
__device__ float g_att[(size_t)ROWS * N_EMBD];    // [8192, 1024] (tf32-rounded)
__device__ float g_xr [(size_t)ROWS * N_EMBD];    // tf32-rounded x
__device__ float g_wqt[(size_t)C3 * N_EMBD];      // W_qkv^T [3072,1024], rounded
__device__ float g_wot[(size_t)N_EMBD * N_EMBD];  // W_out^T [1024,1024], rounded
__device__ float g_vt [(size_t)BATCH * N_HEAD * HEADD * SEQ];  // V^T per head

// ---------------------------------------------------------------------------
__device__ __forceinline__ float to_tf32(float x) {
    uint32_t o;
    asm("cvt.rna.tf32.f32 %0, %1;" : "=r"(o) : "f"(x));
    return __uint_as_float(o);
}
__device__ __forceinline__ uint32_t smem_u32(const void* p) {
    uint32_t a;
    asm("{ .reg .u64 t; cvta.to.shared.u64 t, %1; cvt.u32.u64 %0, t; }" : "=r"(a) : "l"(p));
    return a;
}
__device__ __forceinline__ void cp_async16(uint32_t dst, const float* src) {
    asm volatile("cp.async.cg.shared.global [%0], [%1], 16;" :: "r"(dst), "l"(src));
}
#define CP_COMMIT() asm volatile("cp.async.commit_group;" ::: "memory")
#define CP_WAIT(n)  asm volatile("cp.async.wait_group %0;" :: "n"(n) : "memory")

__device__ __forceinline__ void mma_tf32(float* d, const uint32_t* a, const uint32_t* b) {
    asm volatile(
        "mma.sync.aligned.m16n8k8.row.col.f32.tf32.tf32.f32 "
        "{%0,%1,%2,%3}, {%4,%5,%6,%7}, {%8,%9}, {%0,%1,%2,%3};"
        : "+f"(d[0]), "+f"(d[1]), "+f"(d[2]), "+f"(d[3])
        : "r"(a[0]), "r"(a[1]), "r"(a[2]), "r"(a[3]), "r"(b[0]), "r"(b[1]));
}
__device__ __forceinline__ void ldsm_x4(uint32_t* r, uint32_t addr) {
    asm volatile("ldmatrix.sync.aligned.m8n8.x4.shared.b16 {%0,%1,%2,%3}, [%4];"
                 : "=r"(r[0]), "=r"(r[1]), "=r"(r[2]), "=r"(r[3]) : "r"(addr));
}
__device__ __forceinline__ void ldsm_x2(uint32_t* r, uint32_t addr) {
    asm volatile("ldmatrix.sync.aligned.m8n8.x2.shared.b16 {%0,%1}, [%2];"
                 : "=r"(r[0]), "=r"(r[1]) : "r"(addr));
}

// ---------------------------------------------------------------------------
// pre-pass kernels
// ---------------------------------------------------------------------------
__global__ __launch_bounds__(256) void round_rna(const float* __restrict__ in,
                                                 float* __restrict__ out) {
    int i = blockIdx.x * 256 + threadIdx.x;
    float4 v = ((const float4*)in)[i];
    v.x = to_tf32(v.x); v.y = to_tf32(v.y);
    v.z = to_tf32(v.z); v.w = to_tf32(v.w);
    ((float4*)out)[i] = v;
}

// W[1024][N] -> Wt[N][1024], tf32-rounded
__global__ __launch_bounds__(256) void transpose_rna(const float* __restrict__ W,
                                                     float* __restrict__ Wt, int N) {
    __shared__ float t[32][33];
    const int nx = blockIdx.x * 32, ky = blockIdx.y * 32;
    const int tx = threadIdx.x & 31, ty = threadIdx.x >> 5;
#pragma unroll
    for (int i = 0; i < 32; i += 8)
        t[ty + i][tx] = W[(size_t)(ky + ty + i) * N + nx + tx];
    __syncthreads();
#pragma unroll
    for (int i = 0; i < 32; i += 8)
        Wt[(size_t)(nx + ty + i) * 1024 + ky + tx] = to_tf32(t[tx][ty + i]);
}

// V slice of qkv -> vt[b*16+h][d][t]   (values already tf32-rounded)
__global__ __launch_bounds__(256) void transpose_v(const float* __restrict__ qkv,
                                                   float* __restrict__ vt) {
    __shared__ float t[32][33];
    const int t0 = blockIdx.x * 32;    // token tile
    const int d0 = blockIdx.y * 32;    // headdim tile
    const int bh = blockIdx.z;
    const int b  = bh >> 4, h = bh & 15;
    const int tx = threadIdx.x & 31, ty = threadIdx.x >> 5;
    const float* src = qkv + (size_t)(b * SEQ + t0) * C3 + 2 * N_EMBD + h * HEADD + d0;
#pragma unroll
    for (int i = 0; i < 32; i += 8)
        t[ty + i][tx] = src[(size_t)(ty + i) * C3 + tx];
    __syncthreads();
    float* dst = vt + (size_t)(bh * HEADD + d0) * SEQ + t0;
#pragma unroll
    for (int i = 0; i < 32; i += 8)
        dst[(size_t)(ty + i) * SEQ + tx] = t[tx][ty + i];
}

// ---------------------------------------------------------------------------
// TF32 mma.sync GEMM + bias: C[M,N] = A[M,K] @ Bt[N,K]^T + bias[N]
// (unchanged from round 7)
// ---------------------------------------------------------------------------
#define TS_STRIDE 36
#define T_STAGE   (128 * TS_STRIDE * 4)
#define GEMM_SMEM (3 * 2 * T_STAGE)

template <bool ROUND_OUT>
__global__ __launch_bounds__(256, 2) void gemm_tf32(
    const float* __restrict__ A, const float* __restrict__ Bt,
    const float* __restrict__ bias, float* __restrict__ C,
    int M, int N, int K)
{
    extern __shared__ char smem[];
    const uint32_t sb = smem_u32(smem);

    const int tid  = threadIdx.x;
    const int lane = tid & 31;
    const int warp = tid >> 5;
    const int wm   = (warp >> 2) * 64;
    const int wn   = (warp & 3) * 32;

    const int m0 = blockIdx.y * 128;
    const int n0 = blockIdx.x * 128;

    const int gid = lane >> 2;
    const int gtd = lane & 3;

    float acc[4][4][4];
#pragma unroll
    for (int mi = 0; mi < 4; mi++)
#pragma unroll
        for (int ni = 0; ni < 4; ni++)
#pragma unroll
            for (int r = 0; r < 4; r++) acc[mi][ni][r] = 0.f;

    const uint32_t a_off = ((uint32_t)(lane & 15) * TS_STRIDE +
                            ((uint32_t)(lane >> 4) << 2)) * 4;
    const uint32_t b_off = ((uint32_t)(lane & 7) * TS_STRIDE +
                            (((uint32_t)(lane >> 3) & 1) << 2)) * 4;

#define PREFETCH(c, buf)                                                       \
    {                                                                          \
        const float* Ag = A + (size_t)m0 * K + (c) * 32;                       \
        const float* Bg = Bt + (size_t)n0 * K + (c) * 32;                      \
        const uint32_t sA = sb + (buf) * (2 * T_STAGE);                        \
        const uint32_t sB = sA + T_STAGE;                                      \
        _Pragma("unroll")                                                      \
        for (int i = 0; i < 4; i++) {                                          \
            int s  = tid + i * 256;                                            \
            int r  = s >> 3, kc = (s & 7) << 2;                                \
            cp_async16(sA + (r * TS_STRIDE + kc) * 4,                          \
                       Ag + (size_t)r * K + kc);                               \
            cp_async16(sB + (r * TS_STRIDE + kc) * 4,                          \
                       Bg + (size_t)r * K + kc);                               \
        }                                                                      \
        CP_COMMIT();                                                           \
    }

    const int NK = K >> 5;
    PREFETCH(0, 0);
    PREFETCH(1, 1);

    for (int c = 0; c < NK; c++) {
        if (c + 1 < NK) CP_WAIT(1); else CP_WAIT(0);
        __syncthreads();
        if (c + 2 < NK) PREFETCH(c + 2, (c + 2) % 3);

        const int buf = c % 3;
        const uint32_t sA = sb + buf * (2 * T_STAGE);
        const uint32_t sB = sA + T_STAGE;

#pragma unroll
        for (int kk = 0; kk < 4; kk++) {
            const uint32_t kb4 = (uint32_t)(kk * 8) * 4;
            uint32_t af[4][4];
#pragma unroll
            for (int mi = 0; mi < 4; mi++)
                ldsm_x4(af[mi], sA + (uint32_t)(wm + mi * 16) * TS_STRIDE * 4 +
                                 a_off + kb4);
            uint32_t bf[4][2];
#pragma unroll
            for (int ni = 0; ni < 4; ni++)
                ldsm_x2(bf[ni], sB + (uint32_t)(wn + ni * 8) * TS_STRIDE * 4 +
                                 b_off + kb4);
#pragma unroll
            for (int mi = 0; mi < 4; mi++)
#pragma unroll
                for (int ni = 0; ni < 4; ni++)
                    mma_tf32(acc[mi][ni], af[mi], bf[ni]);
        }
    }

#pragma unroll
    for (int mi = 0; mi < 4; mi++) {
#pragma unroll
        for (int ni = 0; ni < 4; ni++) {
            const int row = m0 + wm + mi * 16 + gid;
            const int col = n0 + wn + ni * 8 + (gtd << 1);
            const float b0 = bias[col];
            const float b1 = bias[col + 1];
            float2 v0, v1;
            v0.x = acc[mi][ni][0] + b0; v0.y = acc[mi][ni][1] + b1;
            v1.x = acc[mi][ni][2] + b0; v1.y = acc[mi][ni][3] + b1;
            if (ROUND_OUT) {
                v0.x = to_tf32(v0.x); v0.y = to_tf32(v0.y);
                v1.x = to_tf32(v1.x); v1.y = to_tf32(v1.y);
            }
            *(float2*)(C + (size_t)row * N + col)       = v0;
            *(float2*)(C + (size_t)(row + 8) * N + col) = v1;
        }
    }
#undef PREFETCH
}

// ---------------------------------------------------------------------------
// Flash attention, causal, TF32 mma.sync, all-ldmatrix fragment path.
// grid: (T/128 reversed, B*H). 256 threads = 8 warps x 16 q rows.
// KV blocks of 64 keys; K from qkv, V from vt (pre-transposed per head).
// P: per-warp smem strip round-trip (STS.64 + ldmatrix), no cross-lane shfl.
// ---------------------------------------------------------------------------
#define KVSTRIDE 68
#define KVBUF    (64 * KVSTRIDE * 2)                       // floats (K + Vt)
#define PSTRIDE  68
#define ATTN_SMEM ((2 * KVBUF + 8 * 16 * PSTRIDE) * 4)     // 104448 B

__global__ __launch_bounds__(256, 2) void attn_mma(
    const float* __restrict__ qkv, const float* __restrict__ vt,
    float* __restrict__ att)
{
    extern __shared__ char smem[];
    float* sm = (float*)smem;
    const uint32_t sb = smem_u32(smem);

    const int qb = gridDim.x - 1 - blockIdx.x;   // heavy CTAs first
    const int b  = blockIdx.y >> 4;
    const int h  = blockIdx.y & 15;

    const int tid  = threadIdx.x;
    const int lane = tid & 31;
    const int warp = tid >> 5;
    const int gid  = lane >> 2;
    const int gtd  = lane & 3;
    const int wq   = warp * 16;

    const float* kbase = qkv + (size_t)(b * SEQ) * C3 + N_EMBD + h * HEADD;
    const float* vtb   = vt + (size_t)((b * N_HEAD + h) * HEADD) * SEQ;

#define PREFETCH_KV(jb, buf)                                                   \
    {                                                                          \
        const float* kp = kbase + (size_t)((jb) * 64) * C3;                    \
        const float* vp = vtb + (jb) * 64;                                     \
        const uint32_t sK = sb + (buf) * (KVBUF * 4);                          \
        const uint32_t sV = sK + 64 * KVSTRIDE * 4;                            \
        _Pragma("unroll")                                                      \
        for (int i = 0; i < 4; i++) {                                          \
            int s = tid + i * 256;                                             \
            int r = s >> 4, c4 = (s & 15) << 2;                                \
            cp_async16(sK + (r * KVSTRIDE + c4) * 4,                           \
                       kp + (size_t)r * C3 + c4);                              \
            cp_async16(sV + (r * KVSTRIDE + c4) * 4,                           \
                       vp + (size_t)r * SEQ + c4);                             \
        }                                                                      \
        CP_COMMIT();                                                           \
    }

    PREFETCH_KV(0, 0);

    // Q fragments (rows qb*128 + wq + gid/+8), pre-scaled by 0.125 (exact)
    uint32_t qf[8][4];
    {
        const float* qp = qkv + (size_t)(b * SEQ + qb * 128) * C3 + h * HEADD;
        const int r0 = wq + gid, r1 = r0 + 8;
#pragma unroll
        for (int ks = 0; ks < 8; ks++) {
            const int c = ks * 8 + gtd;
            qf[ks][0] = __float_as_uint(qp[(size_t)r0 * C3 + c] * 0.125f);
            qf[ks][1] = __float_as_uint(qp[(size_t)r1 * C3 + c] * 0.125f);
            qf[ks][2] = __float_as_uint(qp[(size_t)r0 * C3 + c + 4] * 0.125f);
            qf[ks][3] = __float_as_uint(qp[(size_t)r1 * C3 + c + 4] * 0.125f);
        }
    }

    // per-warp P strip
    float* Pw = sm + 2 * KVBUF + warp * 16 * PSTRIDE;
    const uint32_t sP = sb + (2 * KVBUF + warp * 16 * PSTRIDE) * 4;
    // ldmatrix lane offsets
    const uint32_t bfrag_off = ((uint32_t)((lane >> 4) * 8 + (lane & 7)) * KVSTRIDE +
                                (((uint32_t)(lane >> 3) & 1) << 2)) * 4;  // + ntp*16rows*... added per use
    const uint32_t afrag_off = ((uint32_t)((lane & 7) + ((lane >> 3) & 1) * 8) * PSTRIDE +
                                ((uint32_t)(lane >> 4) << 2)) * 4;

    float m0 = -1e30f, m1 = -1e30f, l0 = 0.f, l1 = 0.f;
    float o[8][4];
#pragma unroll
    for (int dt = 0; dt < 8; dt++)
#pragma unroll
        for (int r = 0; r < 4; r++) o[dt][r] = 0.f;

    const int dw  = 2 * qb + (warp >> 2);    // this warp's diagonal block
    const int NJB = 2 * qb + 2;
    const int rowg0 = qb * 128 + wq + gid;
    const int rowg1 = rowg0 + 8;

    for (int jb = 0; jb < NJB; jb++) {
        CP_WAIT(0);
        __syncthreads();
        if (jb + 1 < NJB) PREFETCH_KV(jb + 1, (jb + 1) & 1);

        const uint32_t sK = sb + (uint32_t)(jb & 1) * (KVBUF * 4);
        const uint32_t sV = sK + 64 * KVSTRIDE * 4;

        if (jb <= dw) {   // warps 0-3 skip the fully-masked last block
            // S = (Q/8) K^T
            float s[8][4];
#pragma unroll
            for (int nt = 0; nt < 8; nt++)
#pragma unroll
                for (int r = 0; r < 4; r++) s[nt][r] = 0.f;

#pragma unroll
            for (int ks = 0; ks < 8; ks++) {
                const uint32_t kb4 = (uint32_t)(ks * 8) * 4;
#pragma unroll
                for (int ntp = 0; ntp < 4; ntp++) {
                    uint32_t kf[4];
                    ldsm_x4(kf, sK + (uint32_t)(ntp * 16) * KVSTRIDE * 4 +
                                 bfrag_off + kb4);
                    mma_tf32(s[2 * ntp],     qf[ks], kf);
                    mma_tf32(s[2 * ntp + 1], qf[ks], kf + 2);
                }
            }

            if (jb == dw) {
#pragma unroll
                for (int nt = 0; nt < 8; nt++) {
                    const int cg = jb * 64 + nt * 8 + gtd * 2;
                    if (cg     > rowg0) s[nt][0] = -1e30f;
                    if (cg + 1 > rowg0) s[nt][1] = -1e30f;
                    if (cg     > rowg1) s[nt][2] = -1e30f;
                    if (cg + 1 > rowg1) s[nt][3] = -1e30f;
                }
            }

            // online softmax
            float mx0 = -1e30f, mx1 = -1e30f;
#pragma unroll
            for (int nt = 0; nt < 8; nt++) {
                mx0 = fmaxf(mx0, fmaxf(s[nt][0], s[nt][1]));
                mx1 = fmaxf(mx1, fmaxf(s[nt][2], s[nt][3]));
            }
            mx0 = fmaxf(mx0, __shfl_xor_sync(0xffffffffu, mx0, 1));
            mx0 = fmaxf(mx0, __shfl_xor_sync(0xffffffffu, mx0, 2));
            mx1 = fmaxf(mx1, __shfl_xor_sync(0xffffffffu, mx1, 1));
            mx1 = fmaxf(mx1, __shfl_xor_sync(0xffffffffu, mx1, 2));

            const float mn0 = fmaxf(m0, mx0), mn1 = fmaxf(m1, mx1);
            const float a0 = __expf(m0 - mn0), a1 = __expf(m1 - mn1);
            m0 = mn0; m1 = mn1;

            float rs0 = 0.f, rs1 = 0.f;
#pragma unroll
            for (int nt = 0; nt < 8; nt++) {
                float p0 = __expf(s[nt][0] - mn0);
                float p1 = __expf(s[nt][1] - mn0);
                float p2 = __expf(s[nt][2] - mn1);
                float p3 = __expf(s[nt][3] - mn1);
                rs0 += p0 + p1; rs1 += p2 + p3;
                float2 lo, hi;
                lo.x = to_tf32(p0); lo.y = to_tf32(p1);
                hi.x = to_tf32(p2); hi.y = to_tf32(p3);
                *(float2*)&Pw[gid * PSTRIDE + nt * 8 + gtd * 2]       = lo;
                *(float2*)&Pw[(gid + 8) * PSTRIDE + nt * 8 + gtd * 2] = hi;
            }
            rs0 += __shfl_xor_sync(0xffffffffu, rs0, 1);
            rs0 += __shfl_xor_sync(0xffffffffu, rs0, 2);
            rs1 += __shfl_xor_sync(0xffffffffu, rs1, 1);
            rs1 += __shfl_xor_sync(0xffffffffu, rs1, 2);
            l0 = l0 * a0 + rs0;
            l1 = l1 * a1 + rs1;

#pragma unroll
            for (int dt = 0; dt < 8; dt++) {
                o[dt][0] *= a0; o[dt][1] *= a0;
                o[dt][2] *= a1; o[dt][3] *= a1;
            }

            __syncwarp();

            // O += P V  (P from smem strip, V from Vt smem, all ldmatrix)
#pragma unroll
            for (int cb = 0; cb < 8; cb++) {
                const uint32_t kb4 = (uint32_t)(cb * 8) * 4;
                uint32_t pf[4];
                ldsm_x4(pf, sP + afrag_off + kb4);
#pragma unroll
                for (int dtp = 0; dtp < 4; dtp++) {
                    uint32_t vf[4];
                    ldsm_x4(vf, sV + (uint32_t)(dtp * 16) * KVSTRIDE * 4 +
                                 bfrag_off + kb4);
                    mma_tf32(o[2 * dtp],     pf, vf);
                    mma_tf32(o[2 * dtp + 1], pf, vf + 2);
                }
            }
        }
    }

    // normalize, round to tf32 (gemm2 consumes raw bits via cp.async), write
    const float inv0 = 1.f / l0, inv1 = 1.f / l1;
    const size_t grow0 = (size_t)(b * SEQ + qb * 128 + wq + gid);
    const int colb = h * HEADD + gtd * 2;
#pragma unroll
    for (int dt = 0; dt < 8; dt++) {
        float2 v0, v1;
        v0.x = to_tf32(o[dt][0] * inv0); v0.y = to_tf32(o[dt][1] * inv0);
        v1.x = to_tf32(o[dt][2] * inv1); v1.y = to_tf32(o[dt][3] * inv1);
        *(float2*)(att + grow0 * N_EMBD + colb + dt * 8)       = v0;
        *(float2*)(att + (grow0 + 8) * N_EMBD + colb + dt * 8) = v1;
    }
#undef PREFETCH_KV
}

// ---------------------------------------------------------------------------
extern "C" void kernel_launch(void* const* d_in, const int* in_sizes, int n_in,
                              void* d_out, int out_size)
{
    const float* x     = (const float*)d_in[0];
    const float* W_qkv = (const float*)d_in[1];
    const float* b_qkv = (const float*)d_in[2];
    const float* W_out = (const float*)d_in[3];
    const float* b_out = (const float*)d_in[4];
    float* out = (float*)d_out;

    float *qkv, *att, *xr, *wqt, *wot, *vt;
    cudaGetSymbolAddress((void**)&qkv, g_qkv);
    cudaGetSymbolAddress((void**)&att, g_att);
    cudaGetSymbolAddress((void**)&xr,  g_xr);
    cudaGetSymbolAddress((void**)&wqt, g_wqt);
    cudaGetSymbolAddress((void**)&wot, g_wot);
    cudaGetSymbolAddress((void**)&vt,  g_vt);

    cudaFuncSetAttribute(gemm_tf32<true>,
                         cudaFuncAttributeMaxDynamicSharedMemorySize, GEMM_SMEM);
    cudaFuncSetAttribute(gemm_tf32<false>,
                         cudaFuncAttributeMaxDynamicSharedMemorySize, GEMM_SMEM);
    cudaFuncSetAttribute(attn_mma,
                         cudaFuncAttributeMaxDynamicSharedMemorySize, ATTN_SMEM);

    // pre-pass: round x; transpose+round weights
    round_rna<<<ROWS * N_EMBD / 1024, 256>>>(x, xr);
    transpose_rna<<<dim3(C3 / 32, N_EMBD / 32), 256>>>(W_qkv, wqt, C3);
    transpose_rna<<<dim3(N_EMBD / 32, N_EMBD / 32), 256>>>(W_out, wot, N_EMBD);

    // 1) qkv = x @ W_qkv + b_qkv  (tf32-rounded output)
    gemm_tf32<true><<<dim3(C3 / 128, ROWS / 128), 256, GEMM_SMEM>>>(
        xr, wqt, b_qkv, qkv, ROWS, C3, N_EMBD);
    // 1b) V^T per head for ldmatrix-friendly attention loads
    transpose_v<<<dim3(SEQ / 32, HEADD / 32, BATCH * N_HEAD), 256>>>(qkv, vt);
    // 2) attention
    attn_mma<<<dim3(SEQ / 128, BATCH * N_HEAD), 256, ATTN_SMEM>>>(qkv, vt, att);
    // 3) out = att @ W_out + b_out  (final output stays fp32)
    gemm_tf32<false><<<dim3(N_EMBD / 128, ROWS / 128), 256, GEMM_SMEM>>>(
        att, wot, b_out, out, ROWS, N_EMBD, N_EMBD);
}

// round 10
// speedup vs baseline: 7.5904x; 1.8460x over previous
#include <cuda_runtime.h>
#include <cuda_fp16.h>
#include <cstdint>
#include <string.h>
#include <math.h>

#define N_EMBD 1024
#define N_HEAD 16
#define HEADD  64
#define BATCH  4
#define SEQ    2048
#define ROWS   (BATCH * SEQ)          // 8192
#define C3     (3 * N_EMBD)           // 3072

// scratch (allocation-free rule: device globals) — fp16 operand copies
__device__ __half g_qkvh[(size_t)ROWS * C3];        // qkv, half
__device__ __half g_atth[(size_t)ROWS * N_EMBD];    // attention out, half
__device__ __half g_xh  [(size_t)ROWS * N_EMBD];    // x, half
__device__ __half g_wqth[(size_t)C3 * N_EMBD];      // W_qkv^T [3072,1024], half
__device__ __half g_woth[(size_t)N_EMBD * N_EMBD];  // W_out^T [1024,1024], half
__device__ __half g_vth [(size_t)BATCH * N_HEAD * HEADD * SEQ];  // V^T per head

// ---------------------------------------------------------------------------
__device__ __forceinline__ uint32_t h2_bits(__half2 v) {
    uint32_t u;
    memcpy(&u, &v, 4);
    return u;
}
__device__ __forceinline__ uint32_t smem_u32(const void* p) {
    uint32_t a;
    asm("{ .reg .u64 t; cvta.to.shared.u64 t, %1; cvt.u32.u64 %0, t; }" : "=r"(a) : "l"(p));
    return a;
}
__device__ __forceinline__ void cp_async16(uint32_t dst, const void* src) {
    asm volatile("cp.async.cg.shared.global [%0], [%1], 16;" :: "r"(dst), "l"(src));
}
#define CP_COMMIT() asm volatile("cp.async.commit_group;" ::: "memory")
#define CP_WAIT(n)  asm volatile("cp.async.wait_group %0;" :: "n"(n) : "memory")

__device__ __forceinline__ void mma_f16(float* d, const uint32_t* a, const uint32_t* b) {
    asm volatile(
        "mma.sync.aligned.m16n8k16.row.col.f32.f16.f16.f32 "
        "{%0,%1,%2,%3}, {%4,%5,%6,%7}, {%8,%9}, {%0,%1,%2,%3};"
        : "+f"(d[0]), "+f"(d[1]), "+f"(d[2]), "+f"(d[3])
        : "r"(a[0]), "r"(a[1]), "r"(a[2]), "r"(a[3]), "r"(b[0]), "r"(b[1]));
}
__device__ __forceinline__ void ldsm_x4(uint32_t* r, uint32_t addr) {
    asm volatile("ldmatrix.sync.aligned.m8n8.x4.shared.b16 {%0,%1,%2,%3}, [%4];"
                 : "=r"(r[0]), "=r"(r[1]), "=r"(r[2]), "=r"(r[3]) : "r"(addr));
}
__device__ __forceinline__ void ldsm_x2(uint32_t* r, uint32_t addr) {
    asm volatile("ldmatrix.sync.aligned.m8n8.x2.shared.b16 {%0,%1}, [%2];"
                 : "=r"(r[0]), "=r"(r[1]) : "r"(addr));
}

// ---------------------------------------------------------------------------
// pre-pass kernels
// ---------------------------------------------------------------------------
__global__ __launch_bounds__(256) void conv_half(const float* __restrict__ in,
                                                 __half2* __restrict__ out) {
    int i = blockIdx.x * 256 + threadIdx.x;
    float4 v = ((const float4*)in)[i];
    out[2 * i]     = __floats2half2_rn(v.x, v.y);
    out[2 * i + 1] = __floats2half2_rn(v.z, v.w);
}

// W[1024][N] float -> Wt[N][1024] half
__global__ __launch_bounds__(256) void transpose_half(const float* __restrict__ W,
                                                      __half* __restrict__ Wt, int N) {
    __shared__ float t[32][33];
    const int nx = blockIdx.x * 32, ky = blockIdx.y * 32;
    const int tx = threadIdx.x & 31, ty = threadIdx.x >> 5;
#pragma unroll
    for (int i = 0; i < 32; i += 8)
        t[ty + i][tx] = W[(size_t)(ky + ty + i) * N + nx + tx];
    __syncthreads();
#pragma unroll
    for (int i = 0; i < 32; i += 8)
        Wt[(size_t)(nx + ty + i) * 1024 + ky + tx] = __float2half_rn(t[tx][ty + i]);
}

// V slice of qkvh -> vth[b*16+h][d][t]
__global__ __launch_bounds__(256) void transpose_v(const __half* __restrict__ qkvh,
                                                   __half* __restrict__ vth) {
    __shared__ __half t[32][34];
    const int t0 = blockIdx.x * 32;
    const int d0 = blockIdx.y * 32;
    const int bh = blockIdx.z;
    const int b  = bh >> 4, h = bh & 15;
    const int tx = threadIdx.x & 31, ty = threadIdx.x >> 5;
    const __half* src = qkvh + (size_t)(b * SEQ + t0) * C3 + 2 * N_EMBD + h * HEADD + d0;
#pragma unroll
    for (int i = 0; i < 32; i += 8)
        t[ty + i][tx] = src[(size_t)(ty + i) * C3 + tx];
    __syncthreads();
    __half* dst = vth + (size_t)(bh * HEADD + d0) * SEQ + t0;
#pragma unroll
    for (int i = 0; i < 32; i += 8)
        dst[(size_t)(ty + i) * SEQ + tx] = t[tx][ty + i];
}

// ---------------------------------------------------------------------------
// FP16 mma.sync GEMM + bias: C[M,N] = A[M,K] @ Bt[N,K]^T + bias[N]
// Both operands half, K-major. 128x128 tile, BK=64 halves, 256 threads.
// ldmatrix fragments, cp.async 3-stage pipeline. fp32 accumulate + bias.
// HALF_OUT: write __half (for MMA consumers); else float.
// ---------------------------------------------------------------------------
#define TSH      72                              // halves per row (144 B)
#define T_STAGE  (128 * TSH * 2)                 // 18432 B per tile
#define GEMM_SMEM (3 * 2 * T_STAGE)              // 110592 B

template <bool HALF_OUT>
__global__ __launch_bounds__(256, 2) void gemm_f16(
    const __half* __restrict__ A, const __half* __restrict__ Bt,
    const float* __restrict__ bias, void* __restrict__ Cv,
    int M, int N, int K)
{
    extern __shared__ char smem[];
    const uint32_t sb = smem_u32(smem);

    const int tid  = threadIdx.x;
    const int lane = tid & 31;
    const int warp = tid >> 5;
    const int wm   = (warp >> 2) * 64;
    const int wn   = (warp & 3) * 32;

    const int m0 = blockIdx.y * 128;
    const int n0 = blockIdx.x * 128;

    const int gid = lane >> 2;
    const int gtd = lane & 3;

    float acc[4][4][4];
#pragma unroll
    for (int mi = 0; mi < 4; mi++)
#pragma unroll
        for (int ni = 0; ni < 4; ni++)
#pragma unroll
            for (int r = 0; r < 4; r++) acc[mi][ni][r] = 0.f;

    // fp16 ldmatrix lane offsets (bytes)
    const uint32_t a_off = (uint32_t)(lane & 15) * (TSH * 2) +
                           ((uint32_t)(lane >> 4) << 4);
    const uint32_t b_off = (uint32_t)(lane & 7) * (TSH * 2) +
                           (((uint32_t)(lane >> 3) & 1) << 4);

#define PREFETCH(c, buf)                                                       \
    {                                                                          \
        const __half* Ag = A + (size_t)m0 * K + (c) * 64;                      \
        const __half* Bg = Bt + (size_t)n0 * K + (c) * 64;                     \
        const uint32_t sA = sb + (buf) * (2 * T_STAGE);                        \
        const uint32_t sB = sA + T_STAGE;                                      \
        _Pragma("unroll")                                                      \
        for (int i = 0; i < 4; i++) {                                          \
            int s  = tid + i * 256;                                            \
            int r  = s >> 3, p = s & 7;                                        \
            cp_async16(sA + r * (TSH * 2) + p * 16,                            \
                       Ag + (size_t)r * K + p * 8);                            \
            cp_async16(sB + r * (TSH * 2) + p * 16,                            \
                       Bg + (size_t)r * K + p * 8);                            \
        }                                                                      \
        CP_COMMIT();                                                           \
    }

    const int NK = K >> 6;   // BK = 64 halves
    PREFETCH(0, 0);
    PREFETCH(1, 1);

    for (int c = 0; c < NK; c++) {
        if (c + 1 < NK) CP_WAIT(1); else CP_WAIT(0);
        __syncthreads();
        if (c + 2 < NK) PREFETCH(c + 2, (c + 2) % 3);

        const int buf = c % 3;
        const uint32_t sA = sb + buf * (2 * T_STAGE);
        const uint32_t sB = sA + T_STAGE;

#pragma unroll
        for (int kk = 0; kk < 4; kk++) {        // 4 x k16
            const uint32_t kb = (uint32_t)kk * 32;   // 16 halves
            uint32_t af[4][4];
#pragma unroll
            for (int mi = 0; mi < 4; mi++)
                ldsm_x4(af[mi], sA + (uint32_t)(wm + mi * 16) * (TSH * 2) +
                                 a_off + kb);
            uint32_t bf[4][2];
#pragma unroll
            for (int ni = 0; ni < 4; ni++)
                ldsm_x2(bf[ni], sB + (uint32_t)(wn + ni * 8) * (TSH * 2) +
                                 b_off + kb);
#pragma unroll
            for (int mi = 0; mi < 4; mi++)
#pragma unroll
                for (int ni = 0; ni < 4; ni++)
                    mma_f16(acc[mi][ni], af[mi], bf[ni]);
        }
    }

    // epilogue: fp32 bias add; store half or float
#pragma unroll
    for (int mi = 0; mi < 4; mi++) {
#pragma unroll
        for (int ni = 0; ni < 4; ni++) {
            const int row = m0 + wm + mi * 16 + gid;
            const int col = n0 + wn + ni * 8 + (gtd << 1);
            const float b0 = bias[col];
            const float b1 = bias[col + 1];
            float v00 = acc[mi][ni][0] + b0, v01 = acc[mi][ni][1] + b1;
            float v10 = acc[mi][ni][2] + b0, v11 = acc[mi][ni][3] + b1;
            if (HALF_OUT) {
                __half* C = (__half*)Cv;
                *(__half2*)(C + (size_t)row * N + col) = __floats2half2_rn(v00, v01);
                *(__half2*)(C + (size_t)(row + 8) * N + col) = __floats2half2_rn(v10, v11);
            } else {
                float* C = (float*)Cv;
                float2 a = {v00, v01}, b2 = {v10, v11};
                *(float2*)(C + (size_t)row * N + col)       = a;
                *(float2*)(C + (size_t)(row + 8) * N + col) = b2;
            }
        }
    }
#undef PREFETCH
}

// ---------------------------------------------------------------------------
// Flash attention, causal, FP16 mma.sync, all-ldmatrix.
// grid: (T/128 reversed, B*H). 256 threads = 8 warps x 16 q rows.
// KV blocks of 64 keys; K from qkvh, V from vth (pre-transposed per head).
// ---------------------------------------------------------------------------
#define KVS       72                                    // halves per row
#define KTILE_B   (64 * KVS * 2)                        // 9216 B
#define KVBUF_B   (2 * KTILE_B)                         // K + Vt per buffer
#define PS        72
#define PSTRIP_B  (16 * PS * 2)                         // 2304 B per warp
#define ATTN_SMEM (2 * KVBUF_B + 8 * PSTRIP_B)          // 55296 B

__global__ __launch_bounds__(256, 2) void attn_mma(
    const __half* __restrict__ qkvh, const __half* __restrict__ vth,
    __half* __restrict__ att)
{
    extern __shared__ char smem[];
    __half* smh = (__half*)smem;
    const uint32_t sb = smem_u32(smem);

    const int qb = gridDim.x - 1 - blockIdx.x;   // heavy CTAs first
    const int b  = blockIdx.y >> 4;
    const int h  = blockIdx.y & 15;

    const int tid  = threadIdx.x;
    const int lane = tid & 31;
    const int warp = tid >> 5;
    const int gid  = lane >> 2;
    const int gtd  = lane & 3;
    const int wq   = warp * 16;

    const __half* kbase = qkvh + (size_t)(b * SEQ) * C3 + N_EMBD + h * HEADD;
    const __half* vtb   = vth + (size_t)((b * N_HEAD + h) * HEADD) * SEQ;

#define PREFETCH_KV(jb, buf)                                                   \
    {                                                                          \
        const __half* kp = kbase + (size_t)((jb) * 64) * C3;                   \
        const __half* vp = vtb + (jb) * 64;                                    \
        const uint32_t sK = sb + (buf) * KVBUF_B;                              \
        const uint32_t sV = sK + KTILE_B;                                      \
        _Pragma("unroll")                                                      \
        for (int i = 0; i < 2; i++) {                                          \
            int s = tid + i * 256;                                             \
            int r = s >> 3, p = s & 7;                                         \
            cp_async16(sK + r * (KVS * 2) + p * 16,                            \
                       kp + (size_t)r * C3 + p * 8);                           \
            cp_async16(sV + r * (KVS * 2) + p * 16,                            \
                       vp + (size_t)r * SEQ + p * 8);                          \
        }                                                                      \
        CP_COMMIT();                                                           \
    }

    PREFETCH_KV(0, 0);

    // Q fragments (half2, scaled by exact 0.125)
    uint32_t qf[4][4];
    {
        const __half* qp = qkvh + (size_t)(b * SEQ + qb * 128) * C3 + h * HEADD;
        const int r0 = wq + gid, r1 = r0 + 8;
        const __half2 sc = __floats2half2_rn(0.125f, 0.125f);
#pragma unroll
        for (int ks = 0; ks < 4; ks++) {
            const int c = ks * 16 + gtd * 2;
            __half2 v;
            v = *(const __half2*)(qp + (size_t)r0 * C3 + c);
            qf[ks][0] = h2_bits(__hmul2(v, sc));
            v = *(const __half2*)(qp + (size_t)r1 * C3 + c);
            qf[ks][1] = h2_bits(__hmul2(v, sc));
            v = *(const __half2*)(qp + (size_t)r0 * C3 + c + 8);
            qf[ks][2] = h2_bits(__hmul2(v, sc));
            v = *(const __half2*)(qp + (size_t)r1 * C3 + c + 8);
            qf[ks][3] = h2_bits(__hmul2(v, sc));
        }
    }

    // per-warp P strip
    __half* Pw = smh + (2 * KVBUF_B + warp * PSTRIP_B) / 2;
    const uint32_t sP = sb + 2 * KVBUF_B + warp * PSTRIP_B;
    // fp16 ldmatrix offsets (bytes)
    const uint32_t bfrag_off = (uint32_t)((lane & 7) + ((lane >> 4) << 3)) * (KVS * 2) +
                               (((uint32_t)(lane >> 3) & 1) << 4);
    const uint32_t afrag_off = (uint32_t)(lane & 15) * (PS * 2) +
                               ((uint32_t)(lane >> 4) << 4);

    float m0 = -1e30f, m1 = -1e30f, l0 = 0.f, l1 = 0.f;
    float o[8][4];
#pragma unroll
    for (int dt = 0; dt < 8; dt++)
#pragma unroll
        for (int r = 0; r < 4; r++) o[dt][r] = 0.f;

    const int dw  = 2 * qb + (warp >> 2);
    const int NJB = 2 * qb + 2;
    const int rowg0 = qb * 128 + wq + gid;
    const int rowg1 = rowg0 + 8;

    for (int jb = 0; jb < NJB; jb++) {
        CP_WAIT(0);
        __syncthreads();
        if (jb + 1 < NJB) PREFETCH_KV(jb + 1, (jb + 1) & 1);

        const uint32_t sK = sb + (uint32_t)(jb & 1) * KVBUF_B;
        const uint32_t sV = sK + KTILE_B;

        if (jb <= dw) {
            // S = (Q/8) K^T
            float s[8][4];
#pragma unroll
            for (int nt = 0; nt < 8; nt++)
#pragma unroll
                for (int r = 0; r < 4; r++) s[nt][r] = 0.f;

#pragma unroll
            for (int ks = 0; ks < 4; ks++) {
                const uint32_t kb = (uint32_t)ks * 32;
#pragma unroll
                for (int ntp = 0; ntp < 4; ntp++) {
                    uint32_t kf[4];
                    ldsm_x4(kf, sK + (uint32_t)(ntp * 16) * (KVS * 2) +
                                 bfrag_off + kb);
                    mma_f16(s[2 * ntp],     qf[ks], kf);
                    mma_f16(s[2 * ntp + 1], qf[ks], kf + 2);
                }
            }

            if (jb == dw) {
#pragma unroll
                for (int nt = 0; nt < 8; nt++) {
                    const int cg = jb * 64 + nt * 8 + gtd * 2;
                    if (cg     > rowg0) s[nt][0] = -1e30f;
                    if (cg + 1 > rowg0) s[nt][1] = -1e30f;
                    if (cg     > rowg1) s[nt][2] = -1e30f;
                    if (cg + 1 > rowg1) s[nt][3] = -1e30f;
                }
            }

            float mx0 = -1e30f, mx1 = -1e30f;
#pragma unroll
            for (int nt = 0; nt < 8; nt++) {
                mx0 = fmaxf(mx0, fmaxf(s[nt][0], s[nt][1]));
                mx1 = fmaxf(mx1, fmaxf(s[nt][2], s[nt][3]));
            }
            mx0 = fmaxf(mx0, __shfl_xor_sync(0xffffffffu, mx0, 1));
            mx0 = fmaxf(mx0, __shfl_xor_sync(0xffffffffu, mx0, 2));
            mx1 = fmaxf(mx1, __shfl_xor_sync(0xffffffffu, mx1, 1));
            mx1 = fmaxf(mx1, __shfl_xor_sync(0xffffffffu, mx1, 2));

            const float mn0 = fmaxf(m0, mx0), mn1 = fmaxf(m1, mx1);
            const float a0 = __expf(m0 - mn0), a1 = __expf(m1 - mn1);
            m0 = mn0; m1 = mn1;

            float rs0 = 0.f, rs1 = 0.f;
#pragma unroll
            for (int nt = 0; nt < 8; nt++) {
                float p0 = __expf(s[nt][0] - mn0);
                float p1 = __expf(s[nt][1] - mn0);
                float p2 = __expf(s[nt][2] - mn1);
                float p3 = __expf(s[nt][3] - mn1);
                rs0 += p0 + p1; rs1 += p2 + p3;
                *(__half2*)&Pw[gid * PS + nt * 8 + gtd * 2] =
                    __floats2half2_rn(p0, p1);
                *(__half2*)&Pw[(gid + 8) * PS + nt * 8 + gtd * 2] =
                    __floats2half2_rn(p2, p3);
            }
            rs0 += __shfl_xor_sync(0xffffffffu, rs0, 1);
            rs0 += __shfl_xor_sync(0xffffffffu, rs0, 2);
            rs1 += __shfl_xor_sync(0xffffffffu, rs1, 1);
            rs1 += __shfl_xor_sync(0xffffffffu, rs1, 2);
            l0 = l0 * a0 + rs0;
            l1 = l1 * a1 + rs1;

#pragma unroll
            for (int dt = 0; dt < 8; dt++) {
                o[dt][0] *= a0; o[dt][1] *= a0;
                o[dt][2] *= a1; o[dt][3] *= a1;
            }

            __syncwarp();

            // O += P V  (P strip + Vt tile, all ldmatrix)
#pragma unroll
            for (int cb = 0; cb < 4; cb++) {       // 4 x k16 over tokens
                const uint32_t kb = (uint32_t)cb * 32;
                uint32_t pf[4];
                ldsm_x4(pf, sP + afrag_off + kb);
#pragma unroll
                for (int dtp = 0; dtp < 4; dtp++) {
                    uint32_t vf[4];
                    ldsm_x4(vf, sV + (uint32_t)(dtp * 16) * (KVS * 2) +
                                 bfrag_off + kb);
                    mma_f16(o[2 * dtp],     pf, vf);
                    mma_f16(o[2 * dtp + 1], pf, vf + 2);
                }
            }
        }
    }

    // normalize, write half output for gemm2
    const float inv0 = 1.f / l0, inv1 = 1.f / l1;
    const size_t grow0 = (size_t)(b * SEQ + qb * 128 + wq + gid);
    const int colb = h * HEADD + gtd * 2;
#pragma unroll
    for (int dt = 0; dt < 8; dt++) {
        *(__half2*)(att + grow0 * N_EMBD + colb + dt * 8) =
            __floats2half2_rn(o[dt][0] * inv0, o[dt][1] * inv0);
        *(__half2*)(att + (grow0 + 8) * N_EMBD + colb + dt * 8) =
            __floats2half2_rn(o[dt][2] * inv1, o[dt][3] * inv1);
    }
#undef PREFETCH_KV
}

// ---------------------------------------------------------------------------
extern "C" void kernel_launch(void* const* d_in, const int* in_sizes, int n_in,
                              void* d_out, int out_size)
{
    const float* x     = (const float*)d_in[0];
    const float* W_qkv = (const float*)d_in[1];
    const float* b_qkv = (const float*)d_in[2];
    const float* W_out = (const float*)d_in[3];
    const float* b_out = (const float*)d_in[4];
    float* out = (float*)d_out;

    __half *qkvh, *atth, *xh, *wqth, *woth, *vth;
    cudaGetSymbolAddress((void**)&qkvh, g_qkvh);
    cudaGetSymbolAddress((void**)&atth, g_atth);
    cudaGetSymbolAddress((void**)&xh,   g_xh);
    cudaGetSymbolAddress((void**)&wqth, g_wqth);
    cudaGetSymbolAddress((void**)&woth, g_woth);
    cudaGetSymbolAddress((void**)&vth,  g_vth);

    cudaFuncSetAttribute(gemm_f16<true>,
                         cudaFuncAttributeMaxDynamicSharedMemorySize, GEMM_SMEM);
    cudaFuncSetAttribute(gemm_f16<false>,
                         cudaFuncAttributeMaxDynamicSharedMemorySize, GEMM_SMEM);
    cudaFuncSetAttribute(attn_mma,
                         cudaFuncAttributeMaxDynamicSharedMemorySize, ATTN_SMEM);

    // pre-pass: convert x to half; transpose+convert weights
    conv_half<<<ROWS * N_EMBD / 1024, 256>>>(x, (__half2*)xh);
    transpose_half<<<dim3(C3 / 32, N_EMBD / 32), 256>>>(W_qkv, wqth, C3);
    transpose_half<<<dim3(N_EMBD / 32, N_EMBD / 32), 256>>>(W_out, woth, N_EMBD);

    // 1) qkv = x @ W_qkv + b_qkv   (half output)
    gemm_f16<true><<<dim3(C3 / 128, ROWS / 128), 256, GEMM_SMEM>>>(
        xh, wqth, b_qkv, qkvh, ROWS, C3, N_EMBD);
    // 1b) V^T per head
    transpose_v<<<dim3(SEQ / 32, HEADD / 32, BATCH * N_HEAD), 256>>>(qkvh, vth);
    // 2) attention (half output)
    attn_mma<<<dim3(SEQ / 128, BATCH * N_HEAD), 256, ATTN_SMEM>>>(qkvh, vth, atth);
    // 3) out = att @ W_out + b_out  (fp32 output)
    gemm_f16<false><<<dim3(N_EMBD / 128, ROWS / 128), 256, GEMM_SMEM>>>(
        atth, woth, b_out, out, ROWS, N_EMBD, N_EMBD);
}

// round 11
// speedup vs baseline: 7.7992x; 1.0275x over previous
#include <cuda_runtime.h>
#include <cuda_fp16.h>
#include <cstdint>
#include <string.h>
#include <math.h>

#define N_EMBD 1024
#define N_HEAD 16
#define HEADD  64
#define BATCH  4
#define SEQ    2048
#define ROWS   (BATCH * SEQ)          // 8192
#define C3     (3 * N_EMBD)           // 3072

// scratch (allocation-free rule: device globals) — fp16 operand copies
__device__ __half g_qkvh[(size_t)ROWS * C3];        // qkv, half
__device__ __half g_atth[(size_t)ROWS * N_EMBD];    // attention out, half
__device__ __half g_xh  [(size_t)ROWS * N_EMBD];    // x, half
__device__ __half g_wqth[(size_t)C3 * N_EMBD];      // W_qkv^T [3072,1024], half
__device__ __half g_woth[(size_t)N_EMBD * N_EMBD];  // W_out^T [1024,1024], half
__device__ __half g_vth [(size_t)BATCH * N_HEAD * HEADD * SEQ];  // V^T per head

// ---------------------------------------------------------------------------
__device__ __forceinline__ uint32_t h2_bits(__half2 v) {
    uint32_t u;
    memcpy(&u, &v, 4);
    return u;
}
__device__ __forceinline__ uint32_t smem_u32(const void* p) {
    uint32_t a;
    asm("{ .reg .u64 t; cvta.to.shared.u64 t, %1; cvt.u32.u64 %0, t; }" : "=r"(a) : "l"(p));
    return a;
}
__device__ __forceinline__ void cp_async16(uint32_t dst, const void* src) {
    asm volatile("cp.async.cg.shared.global [%0], [%1], 16;" :: "r"(dst), "l"(src));
}
#define CP_COMMIT() asm volatile("cp.async.commit_group;" ::: "memory")
#define CP_WAIT(n)  asm volatile("cp.async.wait_group %0;" :: "n"(n) : "memory")

__device__ __forceinline__ void mma_f16(float* d, const uint32_t* a, const uint32_t* b) {
    asm volatile(
        "mma.sync.aligned.m16n8k16.row.col.f32.f16.f16.f32 "
        "{%0,%1,%2,%3}, {%4,%5,%6,%7}, {%8,%9}, {%0,%1,%2,%3};"
        : "+f"(d[0]), "+f"(d[1]), "+f"(d[2]), "+f"(d[3])
        : "r"(a[0]), "r"(a[1]), "r"(a[2]), "r"(a[3]), "r"(b[0]), "r"(b[1]));
}
__device__ __forceinline__ void ldsm_x4(uint32_t* r, uint32_t addr) {
    asm volatile("ldmatrix.sync.aligned.m8n8.x4.shared.b16 {%0,%1,%2,%3}, [%4];"
                 : "=r"(r[0]), "=r"(r[1]), "=r"(r[2]), "=r"(r[3]) : "r"(addr));
}

// ---------------------------------------------------------------------------
// pre-pass kernels
// ---------------------------------------------------------------------------
__global__ __launch_bounds__(256) void conv_half(const float* __restrict__ in,
                                                 __half2* __restrict__ out) {
    int i = blockIdx.x * 256 + threadIdx.x;
    float4 v = ((const float4*)in)[i];
    out[2 * i]     = __floats2half2_rn(v.x, v.y);
    out[2 * i + 1] = __floats2half2_rn(v.z, v.w);
}

// W[1024][N] float -> Wt[N][1024] half
__global__ __launch_bounds__(256) void transpose_half(const float* __restrict__ W,
                                                      __half* __restrict__ Wt, int N) {
    __shared__ float t[32][33];
    const int nx = blockIdx.x * 32, ky = blockIdx.y * 32;
    const int tx = threadIdx.x & 31, ty = threadIdx.x >> 5;
#pragma unroll
    for (int i = 0; i < 32; i += 8)
        t[ty + i][tx] = W[(size_t)(ky + ty + i) * N + nx + tx];
    __syncthreads();
#pragma unroll
    for (int i = 0; i < 32; i += 8)
        Wt[(size_t)(nx + ty + i) * 1024 + ky + tx] = __float2half_rn(t[tx][ty + i]);
}

// V slice of qkvh -> vth[b*16+h][d][t]
__global__ __launch_bounds__(256) void transpose_v(const __half* __restrict__ qkvh,
                                                   __half* __restrict__ vth) {
    __shared__ __half t[32][34];
    const int t0 = blockIdx.x * 32;
    const int d0 = blockIdx.y * 32;
    const int bh = blockIdx.z;
    const int b  = bh >> 4, h = bh & 15;
    const int tx = threadIdx.x & 31, ty = threadIdx.x >> 5;
    const __half* src = qkvh + (size_t)(b * SEQ + t0) * C3 + 2 * N_EMBD + h * HEADD + d0;
#pragma unroll
    for (int i = 0; i < 32; i += 8)
        t[ty + i][tx] = src[(size_t)(ty + i) * C3 + tx];
    __syncthreads();
    __half* dst = vth + (size_t)(bh * HEADD + d0) * SEQ + t0;
#pragma unroll
    for (int i = 0; i < 32; i += 8)
        dst[(size_t)(ty + i) * SEQ + tx] = t[tx][ty + i];
}

// ---------------------------------------------------------------------------
// FP16 mma.sync GEMM + bias: C[M,N] = A[M,K] @ Bt[N,K]^T + bias[N]
// 128x128 tile, BK=64 halves, 256 threads, 3-stage cp.async pipeline,
// software-pipelined ldmatrix fragments (double-buffered af/bf).
// ---------------------------------------------------------------------------
#define TSH      72                              // halves per row (144 B)
#define T_STAGE  (128 * TSH * 2)                 // 18432 B per tile
#define GEMM_SMEM (3 * 2 * T_STAGE)              // 110592 B

template <bool HALF_OUT>
__global__ __launch_bounds__(256, 2) void gemm_f16(
    const __half* __restrict__ A, const __half* __restrict__ Bt,
    const float* __restrict__ bias, void* __restrict__ Cv,
    int M, int N, int K)
{
    extern __shared__ char smem[];
    const uint32_t sb = smem_u32(smem);

    const int tid  = threadIdx.x;
    const int lane = tid & 31;
    const int warp = tid >> 5;
    const int wm   = (warp >> 2) * 64;
    const int wn   = (warp & 3) * 32;

    const int m0 = blockIdx.y * 128;
    const int n0 = blockIdx.x * 128;

    const int gid = lane >> 2;
    const int gtd = lane & 3;

    float acc[4][4][4];
#pragma unroll
    for (int mi = 0; mi < 4; mi++)
#pragma unroll
        for (int ni = 0; ni < 4; ni++)
#pragma unroll
            for (int r = 0; r < 4; r++) acc[mi][ni][r] = 0.f;

    // fp16 ldmatrix lane offsets (bytes)
    // A x4 (16x16): lanes 0-15 rows, lanes 16-31 same rows col+8 halves
    const uint32_t a_off = (uint32_t)(lane & 15) * (TSH * 2) +
                           ((uint32_t)(lane >> 4) << 4);
    // B x4 (two 8-row n-tiles x 16 k): m0/m1 = rows 0-7 (k0,k8), m2/m3 = rows 8-15
    const uint32_t b4_off = (uint32_t)((lane & 7) + ((lane >> 4) << 3)) * (TSH * 2) +
                            (((uint32_t)(lane >> 3) & 1) << 4);

#define PREFETCH(c, buf)                                                       \
    {                                                                          \
        const __half* Ag = A + (size_t)m0 * K + (c) * 64;                      \
        const __half* Bg = Bt + (size_t)n0 * K + (c) * 64;                     \
        const uint32_t pA = sb + (buf) * (2 * T_STAGE);                        \
        const uint32_t pB = pA + T_STAGE;                                      \
        _Pragma("unroll")                                                      \
        for (int i = 0; i < 4; i++) {                                          \
            int s  = tid + i * 256;                                            \
            int r  = s >> 3, p = s & 7;                                        \
            cp_async16(pA + r * (TSH * 2) + p * 16,                            \
                       Ag + (size_t)r * K + p * 8);                            \
            cp_async16(pB + r * (TSH * 2) + p * 16,                            \
                       Bg + (size_t)r * K + p * 8);                            \
        }                                                                      \
        CP_COMMIT();                                                           \
    }

#define LOAD_FRAGS(kk, bufi)                                                   \
    {                                                                          \
        const uint32_t kb = (uint32_t)(kk) * 32;                               \
        _Pragma("unroll")                                                      \
        for (int mi = 0; mi < 4; mi++)                                         \
            ldsm_x4(af[bufi][mi],                                              \
                    sA + (uint32_t)(wm + mi * 16) * (TSH * 2) + a_off + kb);   \
        _Pragma("unroll")                                                      \
        for (int p = 0; p < 2; p++)                                            \
            ldsm_x4(bf[bufi][p],                                               \
                    sB + (uint32_t)(wn + p * 16) * (TSH * 2) + b4_off + kb);   \
    }

    uint32_t af[2][4][4];
    uint32_t bf[2][2][4];

    const int NK = K >> 6;   // BK = 64 halves
    PREFETCH(0, 0);
    PREFETCH(1, 1);

    for (int c = 0; c < NK; c++) {
        if (c + 1 < NK) CP_WAIT(1); else CP_WAIT(0);
        __syncthreads();
        if (c + 2 < NK) PREFETCH(c + 2, (c + 2) % 3);

        const int buf = c % 3;
        const uint32_t sA = sb + buf * (2 * T_STAGE);
        const uint32_t sB = sA + T_STAGE;

        LOAD_FRAGS(0, 0);
#pragma unroll
        for (int kk = 0; kk < 4; kk++) {        // 4 x k16
            if (kk < 3) LOAD_FRAGS(kk + 1, (kk + 1) & 1);
            const int cur = kk & 1;
#pragma unroll
            for (int mi = 0; mi < 4; mi++)
#pragma unroll
                for (int ni = 0; ni < 4; ni++)
                    mma_f16(acc[mi][ni], af[cur][mi],
                            &bf[cur][ni >> 1][(ni & 1) << 1]);
        }
    }

    // epilogue: fp32 bias add; store half or float
#pragma unroll
    for (int mi = 0; mi < 4; mi++) {
#pragma unroll
        for (int ni = 0; ni < 4; ni++) {
            const int row = m0 + wm + mi * 16 + gid;
            const int col = n0 + wn + ni * 8 + (gtd << 1);
            const float b0 = bias[col];
            const float b1 = bias[col + 1];
            float v00 = acc[mi][ni][0] + b0, v01 = acc[mi][ni][1] + b1;
            float v10 = acc[mi][ni][2] + b0, v11 = acc[mi][ni][3] + b1;
            if (HALF_OUT) {
                __half* C = (__half*)Cv;
                *(__half2*)(C + (size_t)row * N + col) = __floats2half2_rn(v00, v01);
                *(__half2*)(C + (size_t)(row + 8) * N + col) = __floats2half2_rn(v10, v11);
            } else {
                float* C = (float*)Cv;
                float2 a = {v00, v01}, b2 = {v10, v11};
                *(float2*)(C + (size_t)row * N + col)       = a;
                *(float2*)(C + (size_t)(row + 8) * N + col) = b2;
            }
        }
    }
#undef PREFETCH
#undef LOAD_FRAGS
}

// ---------------------------------------------------------------------------
// Flash attention, causal, FP16 mma.sync, all-ldmatrix, f16x2 exp2 softmax.
// grid: (T/128 reversed, B*H). 256 threads = 8 warps x 16 q rows.
// ---------------------------------------------------------------------------
#define KVS       72                                    // halves per row
#define KTILE_B   (64 * KVS * 2)                        // 9216 B
#define KVBUF_B   (2 * KTILE_B)                         // K + Vt per buffer
#define PS        72
#define PSTRIP_B  (16 * PS * 2)                         // 2304 B per warp
#define ATTN_SMEM (2 * KVBUF_B + 8 * PSTRIP_B)          // 55296 B

__global__ __launch_bounds__(256, 2) void attn_mma(
    const __half* __restrict__ qkvh, const __half* __restrict__ vth,
    __half* __restrict__ att)
{
    extern __shared__ char smem[];
    __half* smh = (__half*)smem;
    const uint32_t sb = smem_u32(smem);

    const int qb = gridDim.x - 1 - blockIdx.x;   // heavy CTAs first
    const int b  = blockIdx.y >> 4;
    const int h  = blockIdx.y & 15;

    const int tid  = threadIdx.x;
    const int lane = tid & 31;
    const int warp = tid >> 5;
    const int gid  = lane >> 2;
    const int gtd  = lane & 3;
    const int wq   = warp * 16;

    const __half* kbase = qkvh + (size_t)(b * SEQ) * C3 + N_EMBD + h * HEADD;
    const __half* vtb   = vth + (size_t)((b * N_HEAD + h) * HEADD) * SEQ;

#define PREFETCH_KV(jb, buf)                                                   \
    {                                                                          \
        const __half* kp = kbase + (size_t)((jb) * 64) * C3;                   \
        const __half* vp = vtb + (jb) * 64;                                    \
        const uint32_t sK = sb + (buf) * KVBUF_B;                              \
        const uint32_t sV = sK + KTILE_B;                                      \
        _Pragma("unroll")                                                      \
        for (int i = 0; i < 2; i++) {                                          \
            int s = tid + i * 256;                                             \
            int r = s >> 3, p = s & 7;                                         \
            cp_async16(sK + r * (KVS * 2) + p * 16,                            \
                       kp + (size_t)r * C3 + p * 8);                           \
            cp_async16(sV + r * (KVS * 2) + p * 16,                            \
                       vp + (size_t)r * SEQ + p * 8);                          \
        }                                                                      \
        CP_COMMIT();                                                           \
    }

    PREFETCH_KV(0, 0);

    // Q fragments (half2, scaled by exact 0.125)
    uint32_t qf[4][4];
    {
        const __half* qp = qkvh + (size_t)(b * SEQ + qb * 128) * C3 + h * HEADD;
        const int r0 = wq + gid, r1 = r0 + 8;
        const __half2 sc = __floats2half2_rn(0.125f, 0.125f);
#pragma unroll
        for (int ks = 0; ks < 4; ks++) {
            const int c = ks * 16 + gtd * 2;
            __half2 v;
            v = *(const __half2*)(qp + (size_t)r0 * C3 + c);
            qf[ks][0] = h2_bits(__hmul2(v, sc));
            v = *(const __half2*)(qp + (size_t)r1 * C3 + c);
            qf[ks][1] = h2_bits(__hmul2(v, sc));
            v = *(const __half2*)(qp + (size_t)r0 * C3 + c + 8);
            qf[ks][2] = h2_bits(__hmul2(v, sc));
            v = *(const __half2*)(qp + (size_t)r1 * C3 + c + 8);
            qf[ks][3] = h2_bits(__hmul2(v, sc));
        }
    }

    // per-warp P strip
    __half* Pw = smh + (2 * KVBUF_B + warp * PSTRIP_B) / 2;
    const uint32_t sP = sb + 2 * KVBUF_B + warp * PSTRIP_B;
    // fp16 ldmatrix offsets (bytes)
    const uint32_t bfrag_off = (uint32_t)((lane & 7) + ((lane >> 4) << 3)) * (KVS * 2) +
                               (((uint32_t)(lane >> 3) & 1) << 4);
    const uint32_t afrag_off = (uint32_t)(lane & 15) * (PS * 2) +
                               ((uint32_t)(lane >> 4) << 4);

    float m0 = -1e30f, m1 = -1e30f, l0 = 0.f, l1 = 0.f;
    float o[8][4];
#pragma unroll
    for (int dt = 0; dt < 8; dt++)
#pragma unroll
        for (int r = 0; r < 4; r++) o[dt][r] = 0.f;

    const int dw  = 2 * qb + (warp >> 2);
    const int NJB = 2 * qb + 2;
    const int rowg0 = qb * 128 + wq + gid;
    const int rowg1 = rowg0 + 8;
    const float LOG2E = 1.4426950408889634f;

    for (int jb = 0; jb < NJB; jb++) {
        CP_WAIT(0);
        __syncthreads();
        if (jb + 1 < NJB) PREFETCH_KV(jb + 1, (jb + 1) & 1);

        const uint32_t sK = sb + (uint32_t)(jb & 1) * KVBUF_B;
        const uint32_t sV = sK + KTILE_B;

        if (jb <= dw) {
            // S = (Q/8) K^T
            float s[8][4];
#pragma unroll
            for (int nt = 0; nt < 8; nt++)
#pragma unroll
                for (int r = 0; r < 4; r++) s[nt][r] = 0.f;

#pragma unroll
            for (int ks = 0; ks < 4; ks++) {
                const uint32_t kb = (uint32_t)ks * 32;
#pragma unroll
                for (int ntp = 0; ntp < 4; ntp++) {
                    uint32_t kf[4];
                    ldsm_x4(kf, sK + (uint32_t)(ntp * 16) * (KVS * 2) +
                                 bfrag_off + kb);
                    mma_f16(s[2 * ntp],     qf[ks], kf);
                    mma_f16(s[2 * ntp + 1], qf[ks], kf + 2);
                }
            }

            if (jb == dw) {
#pragma unroll
                for (int nt = 0; nt < 8; nt++) {
                    const int cg = jb * 64 + nt * 8 + gtd * 2;
                    if (cg     > rowg0) s[nt][0] = -1e30f;
                    if (cg + 1 > rowg0) s[nt][1] = -1e30f;
                    if (cg     > rowg1) s[nt][2] = -1e30f;
                    if (cg + 1 > rowg1) s[nt][3] = -1e30f;
                }
            }

            float mx0 = -1e30f, mx1 = -1e30f;
#pragma unroll
            for (int nt = 0; nt < 8; nt++) {
                mx0 = fmaxf(mx0, fmaxf(s[nt][0], s[nt][1]));
                mx1 = fmaxf(mx1, fmaxf(s[nt][2], s[nt][3]));
            }
            mx0 = fmaxf(mx0, __shfl_xor_sync(0xffffffffu, mx0, 1));
            mx0 = fmaxf(mx0, __shfl_xor_sync(0xffffffffu, mx0, 2));
            mx1 = fmaxf(mx1, __shfl_xor_sync(0xffffffffu, mx1, 1));
            mx1 = fmaxf(mx1, __shfl_xor_sync(0xffffffffu, mx1, 2));

            const float mn0 = fmaxf(m0, mx0), mn1 = fmaxf(m1, mx1);
            const float a0 = __expf(m0 - mn0), a1 = __expf(m1 - mn1);
            m0 = mn0; m1 = mn1;

            // exp via f16x2 MUFU (half the EX2 instructions); P is fp16 anyway
            const float nm0 = -mn0 * LOG2E, nm1 = -mn1 * LOG2E;
            float rs0 = 0.f, rs1 = 0.f;
#pragma unroll
            for (int nt = 0; nt < 8; nt++) {
                float t0 = fmaf(s[nt][0], LOG2E, nm0);
                float t1 = fmaf(s[nt][1], LOG2E, nm0);
                float t2 = fmaf(s[nt][2], LOG2E, nm1);
                float t3 = fmaf(s[nt][3], LOG2E, nm1);
                __half2 e0 = h2exp2(__floats2half2_rn(t0, t1));
                __half2 e1 = h2exp2(__floats2half2_rn(t2, t3));
                *(__half2*)&Pw[gid * PS + nt * 8 + gtd * 2]       = e0;
                *(__half2*)&Pw[(gid + 8) * PS + nt * 8 + gtd * 2] = e1;
                float2 f0 = __half22float2(e0);
                float2 f1 = __half22float2(e1);
                rs0 += f0.x + f0.y;
                rs1 += f1.x + f1.y;
            }
            rs0 += __shfl_xor_sync(0xffffffffu, rs0, 1);
            rs0 += __shfl_xor_sync(0xffffffffu, rs0, 2);
            rs1 += __shfl_xor_sync(0xffffffffu, rs1, 1);
            rs1 += __shfl_xor_sync(0xffffffffu, rs1, 2);
            l0 = l0 * a0 + rs0;
            l1 = l1 * a1 + rs1;

#pragma unroll
            for (int dt = 0; dt < 8; dt++) {
                o[dt][0] *= a0; o[dt][1] *= a0;
                o[dt][2] *= a1; o[dt][3] *= a1;
            }

            __syncwarp();

            // O += P V  (P strip + Vt tile, all ldmatrix)
#pragma unroll
            for (int cb = 0; cb < 4; cb++) {       // 4 x k16 over tokens
                const uint32_t kb = (uint32_t)cb * 32;
                uint32_t pf[4];
                ldsm_x4(pf, sP + afrag_off + kb);
#pragma unroll
                for (int dtp = 0; dtp < 4; dtp++) {
                    uint32_t vf[4];
                    ldsm_x4(vf, sV + (uint32_t)(dtp * 16) * (KVS * 2) +
                                 bfrag_off + kb);
                    mma_f16(o[2 * dtp],     pf, vf);
                    mma_f16(o[2 * dtp + 1], pf, vf + 2);
                }
            }
        }
    }

    // normalize, write half output for gemm2
    const float inv0 = 1.f / l0, inv1 = 1.f / l1;
    const size_t grow0 = (size_t)(b * SEQ + qb * 128 + wq + gid);
    const int colb = h * HEADD + gtd * 2;
#pragma unroll
    for (int dt = 0; dt < 8; dt++) {
        *(__half2*)(att + grow0 * N_EMBD + colb + dt * 8) =
            __floats2half2_rn(o[dt][0] * inv0, o[dt][1] * inv0);
        *(__half2*)(att + (grow0 + 8) * N_EMBD + colb + dt * 8) =
            __floats2half2_rn(o[dt][2] * inv1, o[dt][3] * inv1);
    }
#undef PREFETCH_KV
}

// ---------------------------------------------------------------------------
extern "C" void kernel_launch(void* const* d_in, const int* in_sizes, int n_in,
                              void* d_out, int out_size)
{
    const float* x     = (const float*)d_in[0];
    const float* W_qkv = (const float*)d_in[1];
    const float* b_qkv = (const float*)d_in[2];
    const float* W_out = (const float*)d_in[3];
    const float* b_out = (const float*)d_in[4];
    float* out = (float*)d_out;

    __half *qkvh, *atth, *xh, *wqth, *woth, *vth;
    cudaGetSymbolAddress((void**)&qkvh, g_qkvh);
    cudaGetSymbolAddress((void**)&atth, g_atth);
    cudaGetSymbolAddress((void**)&xh,   g_xh);
    cudaGetSymbolAddress((void**)&wqth, g_wqth);
    cudaGetSymbolAddress((void**)&woth, g_woth);
    cudaGetSymbolAddress((void**)&vth,  g_vth);

    cudaFuncSetAttribute(gemm_f16<true>,
                         cudaFuncAttributeMaxDynamicSharedMemorySize, GEMM_SMEM);
    cudaFuncSetAttribute(gemm_f16<false>,
                         cudaFuncAttributeMaxDynamicSharedMemorySize, GEMM_SMEM);
    cudaFuncSetAttribute(attn_mma,
                         cudaFuncAttributeMaxDynamicSharedMemorySize, ATTN_SMEM);

    // pre-pass: convert x to half; transpose+convert weights
    conv_half<<<ROWS * N_EMBD / 1024, 256>>>(x, (__half2*)xh);
    transpose_half<<<dim3(C3 / 32, N_EMBD / 32), 256>>>(W_qkv, wqth, C3);
    transpose_half<<<dim3(N_EMBD / 32, N_EMBD / 32), 256>>>(W_out, woth, N_EMBD);

    // 1) qkv = x @ W_qkv + b_qkv   (half output)
    gemm_f16<true><<<dim3(C3 / 128, ROWS / 128), 256, GEMM_SMEM>>>(
        xh, wqth, b_qkv, qkvh, ROWS, C3, N_EMBD);
    // 1b) V^T per head
    transpose_v<<<dim3(SEQ / 32, HEADD / 32, BATCH * N_HEAD), 256>>>(qkvh, vth);
    // 2) attention (half output)
    attn_mma<<<dim3(SEQ / 128, BATCH * N_HEAD), 256, ATTN_SMEM>>>(qkvh, vth, atth);
    // 3) out = att @ W_out + b_out  (fp32 output)
    gemm_f16<false><<<dim3(N_EMBD / 128, ROWS / 128), 256, GEMM_SMEM>>>(
        atth, woth, b_out, out, ROWS, N_EMBD, N_EMBD);
}

// round 12
// speedup vs baseline: 7.9273x; 1.0164x over previous
#include <cuda_runtime.h>
#include <cuda_fp16.h>
#include <cstdint>
#include <string.h>
#include <math.h>

#define N_EMBD 1024
#define N_HEAD 16
#define HEADD  64
#define BATCH  4
#define SEQ    2048
#define ROWS   (BATCH * SEQ)          // 8192
#define C3     (3 * N_EMBD)           // 3072

// scratch (allocation-free rule: device globals) — fp16 operand copies
__device__ __half g_qkvh[(size_t)ROWS * C3];        // qkv, half
__device__ __half g_atth[(size_t)ROWS * N_EMBD];    // attention out, half
__device__ __half g_xh  [(size_t)ROWS * N_EMBD];    // x, half
__device__ __half g_wqth[(size_t)C3 * N_EMBD];      // W_qkv^T [3072,1024], half
__device__ __half g_woth[(size_t)N_EMBD * N_EMBD];  // W_out^T [1024,1024], half
__device__ __half g_vth [(size_t)BATCH * N_HEAD * HEADD * SEQ];  // V^T per head

// ---------------------------------------------------------------------------
__device__ __forceinline__ uint32_t h2_bits(__half2 v) {
    uint32_t u;
    memcpy(&u, &v, 4);
    return u;
}
__device__ __forceinline__ uint32_t smem_u32(const void* p) {
    uint32_t a;
    asm("{ .reg .u64 t; cvta.to.shared.u64 t, %1; cvt.u32.u64 %0, t; }" : "=r"(a) : "l"(p));
    return a;
}
__device__ __forceinline__ void cp_async16(uint32_t dst, const void* src) {
    asm volatile("cp.async.cg.shared.global [%0], [%1], 16;" :: "r"(dst), "l"(src));
}
#define CP_COMMIT() asm volatile("cp.async.commit_group;" ::: "memory")
#define CP_WAIT(n)  asm volatile("cp.async.wait_group %0;" :: "n"(n) : "memory")

__device__ __forceinline__ void mma_f16(float* d, const uint32_t* a, const uint32_t* b) {
    asm volatile(
        "mma.sync.aligned.m16n8k16.row.col.f32.f16.f16.f32 "
        "{%0,%1,%2,%3}, {%4,%5,%6,%7}, {%8,%9}, {%0,%1,%2,%3};"
        : "+f"(d[0]), "+f"(d[1]), "+f"(d[2]), "+f"(d[3])
        : "r"(a[0]), "r"(a[1]), "r"(a[2]), "r"(a[3]), "r"(b[0]), "r"(b[1]));
}
__device__ __forceinline__ void ldsm_x4(uint32_t* r, uint32_t addr) {
    asm volatile("ldmatrix.sync.aligned.m8n8.x4.shared.b16 {%0,%1,%2,%3}, [%4];"
                 : "=r"(r[0]), "=r"(r[1]), "=r"(r[2]), "=r"(r[3]) : "r"(addr));
}

// ---------------------------------------------------------------------------
// pre-pass kernels
// ---------------------------------------------------------------------------
__global__ __launch_bounds__(256) void conv_half(const float* __restrict__ in,
                                                 __half2* __restrict__ out) {
    int i = blockIdx.x * 256 + threadIdx.x;
    float4 v = ((const float4*)in)[i];
    out[2 * i]     = __floats2half2_rn(v.x, v.y);
    out[2 * i + 1] = __floats2half2_rn(v.z, v.w);
}

// W[1024][N] float -> Wt[N][1024] half
__global__ __launch_bounds__(256) void transpose_half(const float* __restrict__ W,
                                                      __half* __restrict__ Wt, int N) {
    __shared__ float t[32][33];
    const int nx = blockIdx.x * 32, ky = blockIdx.y * 32;
    const int tx = threadIdx.x & 31, ty = threadIdx.x >> 5;
#pragma unroll
    for (int i = 0; i < 32; i += 8)
        t[ty + i][tx] = W[(size_t)(ky + ty + i) * N + nx + tx];
    __syncthreads();
#pragma unroll
    for (int i = 0; i < 32; i += 8)
        Wt[(size_t)(nx + ty + i) * 1024 + ky + tx] = __float2half_rn(t[tx][ty + i]);
}

// V slice of qkvh -> vth[b*16+h][d][t]
__global__ __launch_bounds__(256) void transpose_v(const __half* __restrict__ qkvh,
                                                   __half* __restrict__ vth) {
    __shared__ __half t[32][34];
    const int t0 = blockIdx.x * 32;
    const int d0 = blockIdx.y * 32;
    const int bh = blockIdx.z;
    const int b  = bh >> 4, h = bh & 15;
    const int tx = threadIdx.x & 31, ty = threadIdx.x >> 5;
    const __half* src = qkvh + (size_t)(b * SEQ + t0) * C3 + 2 * N_EMBD + h * HEADD + d0;
#pragma unroll
    for (int i = 0; i < 32; i += 8)
        t[ty + i][tx] = src[(size_t)(ty + i) * C3 + tx];
    __syncthreads();
    __half* dst = vth + (size_t)(bh * HEADD + d0) * SEQ + t0;
#pragma unroll
    for (int i = 0; i < 32; i += 8)
        dst[(size_t)(ty + i) * SEQ + tx] = t[tx][ty + i];
}

// ---------------------------------------------------------------------------
// FP16 mma.sync GEMM + bias (unchanged from round 11)
// ---------------------------------------------------------------------------
#define TSH      72                              // halves per row (144 B)
#define T_STAGE  (128 * TSH * 2)                 // 18432 B per tile
#define GEMM_SMEM (3 * 2 * T_STAGE)              // 110592 B

template <bool HALF_OUT>
__global__ __launch_bounds__(256, 2) void gemm_f16(
    const __half* __restrict__ A, const __half* __restrict__ Bt,
    const float* __restrict__ bias, void* __restrict__ Cv,
    int M, int N, int K)
{
    extern __shared__ char smem[];
    const uint32_t sb = smem_u32(smem);

    const int tid  = threadIdx.x;
    const int lane = tid & 31;
    const int warp = tid >> 5;
    const int wm   = (warp >> 2) * 64;
    const int wn   = (warp & 3) * 32;

    const int m0 = blockIdx.y * 128;
    const int n0 = blockIdx.x * 128;

    const int gid = lane >> 2;
    const int gtd = lane & 3;

    float acc[4][4][4];
#pragma unroll
    for (int mi = 0; mi < 4; mi++)
#pragma unroll
        for (int ni = 0; ni < 4; ni++)
#pragma unroll
            for (int r = 0; r < 4; r++) acc[mi][ni][r] = 0.f;

    const uint32_t a_off = (uint32_t)(lane & 15) * (TSH * 2) +
                           ((uint32_t)(lane >> 4) << 4);
    const uint32_t b4_off = (uint32_t)((lane & 7) + ((lane >> 4) << 3)) * (TSH * 2) +
                            (((uint32_t)(lane >> 3) & 1) << 4);

#define PREFETCH(c, buf)                                                       \
    {                                                                          \
        const __half* Ag = A + (size_t)m0 * K + (c) * 64;                      \
        const __half* Bg = Bt + (size_t)n0 * K + (c) * 64;                     \
        const uint32_t pA = sb + (buf) * (2 * T_STAGE);                        \
        const uint32_t pB = pA + T_STAGE;                                      \
        _Pragma("unroll")                                                      \
        for (int i = 0; i < 4; i++) {                                          \
            int s  = tid + i * 256;                                            \
            int r  = s >> 3, p = s & 7;                                        \
            cp_async16(pA + r * (TSH * 2) + p * 16,                            \
                       Ag + (size_t)r * K + p * 8);                            \
            cp_async16(pB + r * (TSH * 2) + p * 16,                            \
                       Bg + (size_t)r * K + p * 8);                            \
        }                                                                      \
        CP_COMMIT();                                                           \
    }

#define LOAD_FRAGS(kk, bufi)                                                   \
    {                                                                          \
        const uint32_t kb = (uint32_t)(kk) * 32;                               \
        _Pragma("unroll")                                                      \
        for (int mi = 0; mi < 4; mi++)                                         \
            ldsm_x4(af[bufi][mi],                                              \
                    sA + (uint32_t)(wm + mi * 16) * (TSH * 2) + a_off + kb);   \
        _Pragma("unroll")                                                      \
        for (int p = 0; p < 2; p++)                                            \
            ldsm_x4(bf[bufi][p],                                               \
                    sB + (uint32_t)(wn + p * 16) * (TSH * 2) + b4_off + kb);   \
    }

    uint32_t af[2][4][4];
    uint32_t bf[2][2][4];

    const int NK = K >> 6;   // BK = 64 halves
    PREFETCH(0, 0);
    PREFETCH(1, 1);

    for (int c = 0; c < NK; c++) {
        if (c + 1 < NK) CP_WAIT(1); else CP_WAIT(0);
        __syncthreads();
        if (c + 2 < NK) PREFETCH(c + 2, (c + 2) % 3);

        const int buf = c % 3;
        const uint32_t sA = sb + buf * (2 * T_STAGE);
        const uint32_t sB = sA + T_STAGE;

        LOAD_FRAGS(0, 0);
#pragma unroll
        for (int kk = 0; kk < 4; kk++) {        // 4 x k16
            if (kk < 3) LOAD_FRAGS(kk + 1, (kk + 1) & 1);
            const int cur = kk & 1;
#pragma unroll
            for (int mi = 0; mi < 4; mi++)
#pragma unroll
                for (int ni = 0; ni < 4; ni++)
                    mma_f16(acc[mi][ni], af[cur][mi],
                            &bf[cur][ni >> 1][(ni & 1) << 1]);
        }
    }

#pragma unroll
    for (int mi = 0; mi < 4; mi++) {
#pragma unroll
        for (int ni = 0; ni < 4; ni++) {
            const int row = m0 + wm + mi * 16 + gid;
            const int col = n0 + wn + ni * 8 + (gtd << 1);
            const float b0 = bias[col];
            const float b1 = bias[col + 1];
            float v00 = acc[mi][ni][0] + b0, v01 = acc[mi][ni][1] + b1;
            float v10 = acc[mi][ni][2] + b0, v11 = acc[mi][ni][3] + b1;
            if (HALF_OUT) {
                __half* C = (__half*)Cv;
                *(__half2*)(C + (size_t)row * N + col) = __floats2half2_rn(v00, v01);
                *(__half2*)(C + (size_t)(row + 8) * N + col) = __floats2half2_rn(v10, v11);
            } else {
                float* C = (float*)Cv;
                float2 a = {v00, v01}, b2 = {v10, v11};
                *(float2*)(C + (size_t)row * N + col)       = a;
                *(float2*)(C + (size_t)(row + 8) * N + col) = b2;
            }
        }
    }
#undef PREFETCH
#undef LOAD_FRAGS
}

// ---------------------------------------------------------------------------
// Flash attention, causal, FP16 mma.sync, all-ldmatrix, f16x2 exp2 softmax.
// 4-stage KV ring, ONE barrier per PAIR of 64-key blocks (warps drift inside
// a pair -> softmax of one warp overlaps HMMA of another on the same SMSP).
// grid: (T/128 reversed, B*H). 256 threads = 8 warps x 16 q rows.
// ---------------------------------------------------------------------------
#define KVS       72                                    // halves per row
#define KTILE_B   (64 * KVS * 2)                        // 9216 B
#define KVBUF_B   (2 * KTILE_B)                         // K + Vt per stage
#define PS        72
#define PSTRIP_B  (16 * PS * 2)                         // 2304 B per warp
#define ATTN_SMEM (4 * KVBUF_B + 8 * PSTRIP_B)          // 92160 B

__global__ __launch_bounds__(256, 2) void attn_mma(
    const __half* __restrict__ qkvh, const __half* __restrict__ vth,
    __half* __restrict__ att)
{
    extern __shared__ char smem[];
    __half* smh = (__half*)smem;
    const uint32_t sb = smem_u32(smem);

    const int qb = gridDim.x - 1 - blockIdx.x;   // heavy CTAs first
    const int b  = blockIdx.y >> 4;
    const int h  = blockIdx.y & 15;

    const int tid  = threadIdx.x;
    const int lane = tid & 31;
    const int warp = tid >> 5;
    const int gid  = lane >> 2;
    const int gtd  = lane & 3;
    const int wq   = warp * 16;

    const __half* kbase = qkvh + (size_t)(b * SEQ) * C3 + N_EMBD + h * HEADD;
    const __half* vtb   = vth + (size_t)((b * N_HEAD + h) * HEADD) * SEQ;

#define PREFETCH_KV(jb, buf)                                                   \
    {                                                                          \
        const __half* kp = kbase + (size_t)((jb) * 64) * C3;                   \
        const __half* vp = vtb + (jb) * 64;                                    \
        const uint32_t sK = sb + (buf) * KVBUF_B;                              \
        const uint32_t sV = sK + KTILE_B;                                      \
        _Pragma("unroll")                                                      \
        for (int i = 0; i < 2; i++) {                                          \
            int s = tid + i * 256;                                             \
            int r = s >> 3, p = s & 7;                                         \
            cp_async16(sK + r * (KVS * 2) + p * 16,                            \
                       kp + (size_t)r * C3 + p * 8);                           \
            cp_async16(sV + r * (KVS * 2) + p * 16,                            \
                       vp + (size_t)r * SEQ + p * 8);                          \
        }                                                                      \
        CP_COMMIT();                                                           \
    }

    PREFETCH_KV(0, 0);
    PREFETCH_KV(1, 1);

    // Q fragments (half2, scaled by exact 0.125)
    uint32_t qf[4][4];
    {
        const __half* qp = qkvh + (size_t)(b * SEQ + qb * 128) * C3 + h * HEADD;
        const int r0 = wq + gid, r1 = r0 + 8;
        const __half2 sc = __floats2half2_rn(0.125f, 0.125f);
#pragma unroll
        for (int ks = 0; ks < 4; ks++) {
            const int c = ks * 16 + gtd * 2;
            __half2 v;
            v = *(const __half2*)(qp + (size_t)r0 * C3 + c);
            qf[ks][0] = h2_bits(__hmul2(v, sc));
            v = *(const __half2*)(qp + (size_t)r1 * C3 + c);
            qf[ks][1] = h2_bits(__hmul2(v, sc));
            v = *(const __half2*)(qp + (size_t)r0 * C3 + c + 8);
            qf[ks][2] = h2_bits(__hmul2(v, sc));
            v = *(const __half2*)(qp + (size_t)r1 * C3 + c + 8);
            qf[ks][3] = h2_bits(__hmul2(v, sc));
        }
    }

    // per-warp P strip (after the 4 KV stages)
    __half* Pw = smh + (4 * KVBUF_B + warp * PSTRIP_B) / 2;
    const uint32_t sP = sb + 4 * KVBUF_B + warp * PSTRIP_B;
    // fp16 ldmatrix offsets (bytes)
    const uint32_t bfrag_off = (uint32_t)((lane & 7) + ((lane >> 4) << 3)) * (KVS * 2) +
                               (((uint32_t)(lane >> 3) & 1) << 4);
    const uint32_t afrag_off = (uint32_t)(lane & 15) * (PS * 2) +
                               ((uint32_t)(lane >> 4) << 4);

    float m0 = -1e30f, m1 = -1e30f, l0 = 0.f, l1 = 0.f;
    float o[8][4];
#pragma unroll
    for (int dt = 0; dt < 8; dt++)
#pragma unroll
        for (int r = 0; r < 4; r++) o[dt][r] = 0.f;

    const int dw  = 2 * qb + (warp >> 2);
    const int NJB = 2 * qb + 2;          // always even
    const int rowg0 = qb * 128 + wq + gid;
    const int rowg1 = rowg0 + 8;
    const float LOG2E = 1.4426950408889634f;

    for (int jb = 0; jb < NJB; jb += 2) {
        CP_WAIT(0);          // blocks jb, jb+1 resident
        __syncthreads();     // visible to all; bufs (jb+2)&3,(jb+3)&3 are free
        if (jb + 2 < NJB) PREFETCH_KV(jb + 2, (jb + 2) & 3);
        if (jb + 3 < NJB) PREFETCH_KV(jb + 3, (jb + 3) & 3);

#pragma unroll
        for (int u = 0; u < 2; u++) {
            const int jj = jb + u;
            if (jj > dw) continue;

            const uint32_t sK = sb + (uint32_t)(jj & 3) * KVBUF_B;
            const uint32_t sV = sK + KTILE_B;

            // S = (Q/8) K^T
            float s[8][4];
#pragma unroll
            for (int nt = 0; nt < 8; nt++)
#pragma unroll
                for (int r = 0; r < 4; r++) s[nt][r] = 0.f;

#pragma unroll
            for (int ks = 0; ks < 4; ks++) {
                const uint32_t kb = (uint32_t)ks * 32;
#pragma unroll
                for (int ntp = 0; ntp < 4; ntp++) {
                    uint32_t kf[4];
                    ldsm_x4(kf, sK + (uint32_t)(ntp * 16) * (KVS * 2) +
                                 bfrag_off + kb);
                    mma_f16(s[2 * ntp],     qf[ks], kf);
                    mma_f16(s[2 * ntp + 1], qf[ks], kf + 2);
                }
            }

            if (jj == dw) {
#pragma unroll
                for (int nt = 0; nt < 8; nt++) {
                    const int cg = jj * 64 + nt * 8 + gtd * 2;
                    if (cg     > rowg0) s[nt][0] = -1e30f;
                    if (cg + 1 > rowg0) s[nt][1] = -1e30f;
                    if (cg     > rowg1) s[nt][2] = -1e30f;
                    if (cg + 1 > rowg1) s[nt][3] = -1e30f;
                }
            }

            float mx0 = -1e30f, mx1 = -1e30f;
#pragma unroll
            for (int nt = 0; nt < 8; nt++) {
                mx0 = fmaxf(mx0, fmaxf(s[nt][0], s[nt][1]));
                mx1 = fmaxf(mx1, fmaxf(s[nt][2], s[nt][3]));
            }
            mx0 = fmaxf(mx0, __shfl_xor_sync(0xffffffffu, mx0, 1));
            mx0 = fmaxf(mx0, __shfl_xor_sync(0xffffffffu, mx0, 2));
            mx1 = fmaxf(mx1, __shfl_xor_sync(0xffffffffu, mx1, 1));
            mx1 = fmaxf(mx1, __shfl_xor_sync(0xffffffffu, mx1, 2));

            const float mn0 = fmaxf(m0, mx0), mn1 = fmaxf(m1, mx1);
            const float a0 = __expf(m0 - mn0), a1 = __expf(m1 - mn1);
            m0 = mn0; m1 = mn1;

            // exp via f16x2 MUFU; P is fp16 anyway
            const float nm0 = -mn0 * LOG2E, nm1 = -mn1 * LOG2E;
            float rs0 = 0.f, rs1 = 0.f;
#pragma unroll
            for (int nt = 0; nt < 8; nt++) {
                float t0 = fmaf(s[nt][0], LOG2E, nm0);
                float t1 = fmaf(s[nt][1], LOG2E, nm0);
                float t2 = fmaf(s[nt][2], LOG2E, nm1);
                float t3 = fmaf(s[nt][3], LOG2E, nm1);
                __half2 e0 = h2exp2(__floats2half2_rn(t0, t1));
                __half2 e1 = h2exp2(__floats2half2_rn(t2, t3));
                *(__half2*)&Pw[gid * PS + nt * 8 + gtd * 2]       = e0;
                *(__half2*)&Pw[(gid + 8) * PS + nt * 8 + gtd * 2] = e1;
                float2 f0 = __half22float2(e0);
                float2 f1 = __half22float2(e1);
                rs0 += f0.x + f0.y;
                rs1 += f1.x + f1.y;
            }
            rs0 += __shfl_xor_sync(0xffffffffu, rs0, 1);
            rs0 += __shfl_xor_sync(0xffffffffu, rs0, 2);
            rs1 += __shfl_xor_sync(0xffffffffu, rs1, 1);
            rs1 += __shfl_xor_sync(0xffffffffu, rs1, 2);
            l0 = l0 * a0 + rs0;
            l1 = l1 * a1 + rs1;

#pragma unroll
            for (int dt = 0; dt < 8; dt++) {
                o[dt][0] *= a0; o[dt][1] *= a0;
                o[dt][2] *= a1; o[dt][3] *= a1;
            }

            __syncwarp();

            // O += P V  (P strip + Vt tile, all ldmatrix)
#pragma unroll
            for (int cb = 0; cb < 4; cb++) {       // 4 x k16 over tokens
                const uint32_t kb = (uint32_t)cb * 32;
                uint32_t pf[4];
                ldsm_x4(pf, sP + afrag_off + kb);
#pragma unroll
                for (int dtp = 0; dtp < 4; dtp++) {
                    uint32_t vf[4];
                    ldsm_x4(vf, sV + (uint32_t)(dtp * 16) * (KVS * 2) +
                                 bfrag_off + kb);
                    mma_f16(o[2 * dtp],     pf, vf);
                    mma_f16(o[2 * dtp + 1], pf, vf + 2);
                }
            }
        }
    }

    // normalize, write half output for gemm2
    const float inv0 = 1.f / l0, inv1 = 1.f / l1;
    const size_t grow0 = (size_t)(b * SEQ + qb * 128 + wq + gid);
    const int colb = h * HEADD + gtd * 2;
#pragma unroll
    for (int dt = 0; dt < 8; dt++) {
        *(__half2*)(att + grow0 * N_EMBD + colb + dt * 8) =
            __floats2half2_rn(o[dt][0] * inv0, o[dt][1] * inv0);
        *(__half2*)(att + (grow0 + 8) * N_EMBD + colb + dt * 8) =
            __floats2half2_rn(o[dt][2] * inv1, o[dt][3] * inv1);
    }
#undef PREFETCH_KV
}

// ---------------------------------------------------------------------------
extern "C" void kernel_launch(void* const* d_in, const int* in_sizes, int n_in,
                              void* d_out, int out_size)
{
    const float* x     = (const float*)d_in[0];
    const float* W_qkv = (const float*)d_in[1];
    const float* b_qkv = (const float*)d_in[2];
    const float* W_out = (const float*)d_in[3];
    const float* b_out = (const float*)d_in[4];
    float* out = (float*)d_out;

    __half *qkvh, *atth, *xh, *wqth, *woth, *vth;
    cudaGetSymbolAddress((void**)&qkvh, g_qkvh);
    cudaGetSymbolAddress((void**)&atth, g_atth);
    cudaGetSymbolAddress((void**)&xh,   g_xh);
    cudaGetSymbolAddress((void**)&wqth, g_wqth);
    cudaGetSymbolAddress((void**)&woth, g_woth);
    cudaGetSymbolAddress((void**)&vth,  g_vth);

    cudaFuncSetAttribute(gemm_f16<true>,
                         cudaFuncAttributeMaxDynamicSharedMemorySize, GEMM_SMEM);
    cudaFuncSetAttribute(gemm_f16<false>,
                         cudaFuncAttributeMaxDynamicSharedMemorySize, GEMM_SMEM);
    cudaFuncSetAttribute(attn_mma,
                         cudaFuncAttributeMaxDynamicSharedMemorySize, ATTN_SMEM);

    // pre-pass: convert x to half; transpose+convert weights
    conv_half<<<ROWS * N_EMBD / 1024, 256>>>(x, (__half2*)xh);
    transpose_half<<<dim3(C3 / 32, N_EMBD / 32), 256>>>(W_qkv, wqth, C3);
    transpose_half<<<dim3(N_EMBD / 32, N_EMBD / 32), 256>>>(W_out, woth, N_EMBD);

    // 1) qkv = x @ W_qkv + b_qkv   (half output)
    gemm_f16<true><<<dim3(C3 / 128, ROWS / 128), 256, GEMM_SMEM>>>(
        xh, wqth, b_qkv, qkvh, ROWS, C3, N_EMBD);
    // 1b) V^T per head
    transpose_v<<<dim3(SEQ / 32, HEADD / 32, BATCH * N_HEAD), 256>>>(qkvh, vth);
    // 2) attention (half output)
    attn_mma<<<dim3(SEQ / 128, BATCH * N_HEAD), 256, ATTN_SMEM>>>(qkvh, vth, atth);
    // 3) out = att @ W_out + b_out  (fp32 output)
    gemm_f16<false><<<dim3(N_EMBD / 128, ROWS / 128), 256, GEMM_SMEM>>>(
        atth, woth, b_out, out, ROWS, N_EMBD, N_EMBD);
}